// round 10
// baseline (speedup 1.0000x reference)
#include <cuda_runtime.h>
#include <cstdint>

#define NIMG 64
#define CCH  256
#define HH28 28
#define HWSZ 784
#define NHW  50176
#define NT2  196          // winograd tiles per image (14x14)
#define MWIN 12544        // 64*196 tile-rows
#define UPLANE (MWIN * CCH)   // bytes per U[t] plane (int8)
#define VPLANE (CCH * CCH)

// wino gemm smem: 3 stages, each A(64 x 144B) + B(64 x 144B)  (K-chunk = 128)
#define AROW 144
#define HALF_BYTES (64 * AROW)
#define STAGE (2 * HALF_BYTES)
#define GEMM_SMEM (3 * STAGE)

// ---------------------------------------------------------------- helpers
__device__ __forceinline__ uint32_t smem_u32(const void* p) {
    uint32_t a;
    asm("{ .reg .u64 t; cvta.to.shared.u64 t, %1; cvt.u32.u64 %0, t; }" : "=r"(a) : "l"(p));
    return a;
}
__device__ __forceinline__ void cpa16(uint32_t dst, const void* src) {
    asm volatile("cp.async.cg.shared.global [%0], [%1], 16;"
                 :: "r"(dst), "l"(src) : "memory");
}
__device__ __forceinline__ void mma_s8(int* d, const uint32_t* a, const uint32_t* b) {
    asm volatile(
        "mma.sync.aligned.m16n8k32.row.col.s32.s8.s8.s32 "
        "{%0,%1,%2,%3}, {%4,%5,%6,%7}, {%8,%9}, {%0,%1,%2,%3};"
        : "+r"(d[0]), "+r"(d[1]), "+r"(d[2]), "+r"(d[3])
        : "r"(a[0]), "r"(a[1]), "r"(a[2]), "r"(a[3]), "r"(b[0]), "r"(b[1]));
}
__device__ __forceinline__ uint2 v2add(uint2 a, uint2 b) {
    return make_uint2(__vadd4(a.x, b.x), __vadd4(a.y, b.y));
}
__device__ __forceinline__ uint2 v2sub(uint2 a, uint2 b) {
    return make_uint2(__vsub4(a.x, b.x), __vsub4(a.y, b.y));
}

// ---------------------------------------------------------------- scratch
__device__ __align__(256) char  g_xb1[(size_t)NHW * CCH];   // binarized x, NHWC int8
__device__ __align__(256) char  g_xb2[(size_t)NHW * CCH];   // binarized BN1 out, NHWC int8
__device__ __align__(256) char  g_U[(size_t)16 * UPLANE];   // winograd input transform
__device__ __align__(256) char  g_V1[16 * VPLANE];          // winograd weight transform
__device__ __align__(256) char  g_V2[16 * VPLANE];
__device__ float g_xT[(size_t)CCH * NHW];                   // residual, [c][m]
__device__ short g_y1[(size_t)CCH * NHW];                   // conv1 out, col-major
__device__ float g_y2[(size_t)CCH * NHW];                   // conv2+resid, col-major
__device__ float g_s1[CCH], g_bi1[CCH], g_s2[CCH], g_bi2[CCH];

// -------- K1: binarize x -> NHWC int8, residual -> [c][m] fp32
__global__ void prep_x_kernel(const float* __restrict__ x,
                              char* __restrict__ xb1,
                              float* __restrict__ xT) {
    __shared__ float t[32][33];
    int tx = threadIdx.x, ty = threadIdx.y;
    int n  = blockIdx.z;
    int c0 = blockIdx.y * 32;
    int p0 = blockIdx.x * 32;
    #pragma unroll
    for (int j = 0; j < 4; j++) {
        int c = c0 + ty + j * 8;
        int p = p0 + tx;
        float v = 0.f;
        if (p < HWSZ) {
            v = x[((size_t)n * CCH + c) * HWSZ + p];
            xT[(size_t)c * NHW + n * HWSZ + p] = v;
        }
        t[ty + j * 8][tx] = v;
    }
    __syncthreads();
    #pragma unroll
    for (int j = 0; j < 4; j++) {
        int p = p0 + ty + j * 8;
        if (p < HWSZ) {
            float v = t[tx][ty + j * 8];
            xb1[((size_t)(n * HWSZ + p)) * CCH + c0 + tx] = (v >= 0.f) ? 1 : -1;
        }
    }
}

// -------- wino V: w (OIHW f32) -> V[t][cout*256+cin] int8, V = (2G) sign(w) (2G)^T
__global__ void wino_v_kernel(const float* __restrict__ w, char* __restrict__ V) {
    int idx = blockIdx.x * 256 + threadIdx.x;   // cout*256 + cin
    const float* p = w + (size_t)idx * 9;
    int b[3][3];
    #pragma unroll
    for (int i = 0; i < 3; i++)
        #pragma unroll
        for (int j = 0; j < 3; j++)
            b[i][j] = (p[i * 3 + j] >= 0.f) ? 1 : -1;
    int g[4][3];
    #pragma unroll
    for (int j = 0; j < 3; j++) {
        g[0][j] = 2 * b[0][j];
        g[1][j] = b[0][j] + b[1][j] + b[2][j];
        g[2][j] = b[0][j] - b[1][j] + b[2][j];
        g[3][j] = 2 * b[2][j];
    }
    #pragma unroll
    for (int i = 0; i < 4; i++) {
        int v0 = 2 * g[i][0];
        int v1 = g[i][0] + g[i][1] + g[i][2];
        int v2 = g[i][0] - g[i][1] + g[i][2];
        int v3 = 2 * g[i][2];
        V[(size_t)(i * 4 + 0) * VPLANE + idx] = (char)v0;
        V[(size_t)(i * 4 + 1) * VPLANE + idx] = (char)v1;
        V[(size_t)(i * 4 + 2) * VPLANE + idx] = (char)v2;
        V[(size_t)(i * 4 + 3) * VPLANE + idx] = (char)v3;
    }
}

// -------- wino U: xb NHWC int8 -> U[t][tile*256+c] int8  (B^T d B, |U|<=4)
// 8 channels (uint2) per thread
__global__ void wino_u_kernel(const char* __restrict__ xb, char* __restrict__ U) {
    int item = blockIdx.x * 256 + threadIdx.x;   // tile*32 + cgroup
    int tile = item >> 5;
    int cg = item & 31;                          // 8 channels per thread
    int n = tile / NT2;
    int rt = tile - n * NT2;
    int ty = rt / 14, tx = rt - ty * 14;
    int h0 = 2 * ty - 1, w0 = 2 * tx - 1;
    const char* base = xb + ((size_t)n * HWSZ) * CCH + cg * 8;

    uint2 d[4][4];
    #pragma unroll
    for (int i = 0; i < 4; i++) {
        int h = h0 + i;
        #pragma unroll
        for (int j = 0; j < 4; j++) {
            int w = w0 + j;
            d[i][j] = (((unsigned)h < 28u) & ((unsigned)w < 28u))
                ? *reinterpret_cast<const uint2*>(base + (size_t)(h * HH28 + w) * CCH)
                : make_uint2(0u, 0u);
        }
    }
    uint2 r[4][4];
    #pragma unroll
    for (int j = 0; j < 4; j++) {
        r[0][j] = v2sub(d[0][j], d[2][j]);
        r[1][j] = v2add(d[1][j], d[2][j]);
        r[2][j] = v2sub(d[2][j], d[1][j]);
        r[3][j] = v2sub(d[1][j], d[3][j]);
    }
    size_t off = (size_t)tile * CCH + cg * 8;
    #pragma unroll
    for (int i = 0; i < 4; i++) {
        uint2 u0 = v2sub(r[i][0], r[i][2]);
        uint2 u1 = v2add(r[i][1], r[i][2]);
        uint2 u2 = v2sub(r[i][2], r[i][1]);
        uint2 u3 = v2sub(r[i][1], r[i][3]);
        *reinterpret_cast<uint2*>(U + (size_t)(i * 4 + 0) * UPLANE + off) = u0;
        *reinterpret_cast<uint2*>(U + (size_t)(i * 4 + 1) * UPLANE + off) = u1;
        *reinterpret_cast<uint2*>(U + (size_t)(i * 4 + 2) * UPLANE + off) = u2;
        *reinterpret_cast<uint2*>(U + (size_t)(i * 4 + 3) * UPLANE + off) = u3;
    }
}

// -------- wino GEMM: for t in 0..15: Mhat = U[t]*V[t]^T, fold into Y, write col-major
// grid (196, 4); K-chunk=128, 32 chunks, 3-stage cp.async pipeline, 1 sync/chunk
template <bool RESID>
__global__ void __launch_bounds__(256, 2)
wino_gemm(const char* __restrict__ U,
          const char* __restrict__ V,
          const float* __restrict__ resid,
          void* __restrict__ outp) {
    extern __shared__ __align__(16) char sm[];

    int tid = threadIdx.x, wid = tid >> 5, lane = tid & 31;
    int g = lane >> 2, tg = lane & 3;
    int warpM = wid & 3, warpN = wid >> 2;    // 4 x 2 warps, warp tile 16x32

    // cp.async mapping: per matrix, thread owns units tid and tid+256
    // unit -> row = unit>>3 (0..63), u = unit&7 (16B column)
    const char* srcA[2];
    const char* srcB[2];
    uint32_t dstA[2], dstB[2];
    uint32_t smb = smem_u32(sm);
    #pragma unroll
    for (int i = 0; i < 2; i++) {
        int unit = tid + 256 * i;
        int row = unit >> 3, u = unit & 7;
        srcA[i] = U + ((size_t)blockIdx.x * 64 + row) * CCH + u * 16;
        srcB[i] = V + ((size_t)blockIdx.y * 64 + row) * CCH + u * 16;
        dstA[i] = smb + row * AROW + u * 16;
        dstB[i] = dstA[i] + HALF_BYTES;
    }

    auto issue = [&](int chunk, int s) {
        int t = chunk >> 1, kc = chunk & 1;
        size_t offU = (size_t)t * UPLANE + kc * 128;
        size_t offV = (size_t)t * VPLANE + kc * 128;
        uint32_t so = s * STAGE;
        #pragma unroll
        for (int i = 0; i < 2; i++) {
            cpa16(dstA[i] + so, srcA[i] + offU);
            cpa16(dstB[i] + so, srcB[i] + offV);
        }
        asm volatile("cp.async.commit_group;" ::: "memory");
    };

    int Y[4][4][4];
    int acc[4][4];
    #pragma unroll
    for (int ni = 0; ni < 4; ni++)
        #pragma unroll
        for (int j = 0; j < 4; j++) {
            acc[ni][j] = 0;
            #pragma unroll
            for (int p = 0; p < 4; p++) Y[ni][j][p] = 0;
        }

    issue(0, 0);
    issue(1, 1);
    #pragma unroll 1
    for (int chunk = 0; chunk < 32; ++chunk) {
        int s = chunk % 3;
        if (chunk < 31) {
            asm volatile("cp.async.wait_group 1;" ::: "memory");
        } else {
            asm volatile("cp.async.wait_group 0;" ::: "memory");
        }
        __syncthreads();
        if (chunk < 30) issue(chunk + 2, (chunk + 2) % 3);

        const char* As = sm + s * STAGE;
        const char* Bs = As + HALF_BYTES;
        #pragma unroll
        for (int ks = 0; ks < 4; ks++) {
            int ko = ks * 32;
            uint32_t a[4], b[4][2];
            {
                int r = warpM * 16 + g;
                a[0] = *reinterpret_cast<const uint32_t*>(As + r * AROW + ko + tg * 4);
                a[1] = *reinterpret_cast<const uint32_t*>(As + (r + 8) * AROW + ko + tg * 4);
                a[2] = *reinterpret_cast<const uint32_t*>(As + r * AROW + ko + 16 + tg * 4);
                a[3] = *reinterpret_cast<const uint32_t*>(As + (r + 8) * AROW + ko + 16 + tg * 4);
            }
            #pragma unroll
            for (int ni = 0; ni < 4; ni++) {
                int c = warpN * 32 + ni * 8 + g;
                b[ni][0] = *reinterpret_cast<const uint32_t*>(Bs + c * AROW + ko + tg * 4);
                b[ni][1] = *reinterpret_cast<const uint32_t*>(Bs + c * AROW + ko + 16 + tg * 4);
            }
            #pragma unroll
            for (int ni = 0; ni < 4; ni++)
                mma_s8(acc[ni], a, b[ni]);
        }

        if (chunk & 1) {
            // fold Mhat (acc) of t = chunk>>1 into Y, reset acc
            int t = chunk >> 1;
            int tr = t >> 2, tc = t & 3;
            int cr0 = (tr <= 2) ? 1 : 0;
            int cr1 = (tr == 0) ? 0 : ((tr == 1) ? 1 : -1);
            int cc0 = (tc <= 2) ? 1 : 0;
            int cc1 = (tc == 0) ? 0 : ((tc == 1) ? 1 : -1);
            #pragma unroll
            for (int ni = 0; ni < 4; ni++)
                #pragma unroll
                for (int j = 0; j < 4; j++) {
                    int v = acc[ni][j];
                    Y[ni][j][0] += cr0 * cc0 * v;
                    Y[ni][j][1] += cr0 * cc1 * v;
                    Y[ni][j][2] += cr1 * cc0 * v;
                    Y[ni][j][3] += cr1 * cc1 * v;
                    acc[ni][j] = 0;
                }
        }
    }

    // epilogue: each Mhat element -> 2x2 output pixels, col-major [c][m]
    #pragma unroll
    for (int j = 0; j < 4; j++) {
        int mp = blockIdx.x * 64 + warpM * 16 + g + 8 * (j >> 1);  // wino row
        int n = mp / NT2;
        int rt = mp - n * NT2;
        int ty = rt / 14, tx = rt - ty * 14;
        int mbase = n * HWSZ + (2 * ty) * HH28 + 2 * tx;
        #pragma unroll
        for (int ni = 0; ni < 4; ni++) {
            int c = blockIdx.y * 64 + warpN * 32 + ni * 8 + 2 * tg + (j & 1);
            size_t obase = (size_t)c * NHW + mbase;
            #pragma unroll
            for (int p = 0; p < 4; p++) {
                size_t o = obase + (p >> 1) * HH28 + (p & 1);
                int val = Y[ni][j][p] >> 2;   // exact /4
                if (RESID) {
                    reinterpret_cast<float*>(outp)[o] = (float)val + resid[o];
                } else {
                    reinterpret_cast<short*>(outp)[o] = (short)val;
                }
            }
        }
    }
}

// -------- stats: per-channel fused BN scale/bias
template <typename T>
__global__ void stats_kernel(const T* __restrict__ ycm,
                             const float* __restrict__ gamma, const float* __restrict__ beta,
                             float* __restrict__ scl, float* __restrict__ bia) {
    int c = blockIdx.x;
    const T* p = ycm + (size_t)c * NHW;
    float s = 0.f, q = 0.f;
    for (int i = threadIdx.x; i < NHW; i += 256) {
        float v = (float)p[i];
        s += v; q += v * v;
    }
    __shared__ float rs[256], rq[256];
    rs[threadIdx.x] = s; rq[threadIdx.x] = q;
    __syncthreads();
    for (int o = 128; o > 0; o >>= 1) {
        if (threadIdx.x < o) { rs[threadIdx.x] += rs[threadIdx.x + o]; rq[threadIdx.x] += rq[threadIdx.x + o]; }
        __syncthreads();
    }
    if (threadIdx.x == 0) {
        float mean = rs[0] / (float)NHW;
        float var  = rq[0] / (float)NHW - mean * mean;
        float inv  = rsqrtf(var + 1e-5f);
        float sc   = gamma[c] * inv;
        scl[c] = sc;
        bia[c] = beta[c] - mean * sc;
    }
}

// -------- binarize BN1 output: [c][m] int16 -> [m][c] int8 +-1
__global__ void binarize_kernel(const short* __restrict__ ycm,
                                const float* __restrict__ scl, const float* __restrict__ bia,
                                char* __restrict__ xb2) {
    __shared__ short t[32][33];
    __shared__ float sc[32], bi[32];
    int tx = threadIdx.x, ty = threadIdx.y;
    int c0 = blockIdx.y * 32, m0 = blockIdx.x * 32;
    if (ty == 0) { sc[tx] = scl[c0 + tx]; bi[tx] = bia[c0 + tx]; }
    #pragma unroll
    for (int j = 0; j < 4; j++) {
        int c = c0 + ty + j * 8;
        t[ty + j * 8][tx] = ycm[(size_t)c * NHW + m0 + tx];
    }
    __syncthreads();
    #pragma unroll
    for (int j = 0; j < 4; j++) {
        int m = m0 + ty + j * 8;
        float v = (float)t[tx][ty + j * 8] * sc[tx] + bi[tx];
        xb2[(size_t)m * CCH + c0 + tx] = (v >= 0.f) ? 1 : -1;
    }
}

// -------- final: BN2 + hardtanh + NCHW
__global__ void final_kernel(const float* __restrict__ y2,
                             const float* __restrict__ scl, const float* __restrict__ bia,
                             float* __restrict__ out) {
    size_t total = (size_t)CCH * NHW;
    for (size_t idx = (size_t)blockIdx.x * blockDim.x + threadIdx.x; idx < total;
         idx += (size_t)gridDim.x * blockDim.x) {
        unsigned c = (unsigned)(idx / NHW);
        unsigned r = (unsigned)(idx - (size_t)c * NHW);
        unsigned n = r / HWSZ;
        unsigned hw = r - n * HWSZ;
        float v = y2[idx] * scl[c] + bia[c];
        v = fminf(fmaxf(v, -1.f), 1.f);
        out[((size_t)n * CCH + c) * HWSZ + hw] = v;
    }
}

// ---------------------------------------------------------------- launcher
extern "C" void kernel_launch(void* const* d_in, const int* in_sizes, int n_in,
                              void* d_out, int out_size) {
    const float* x   = (const float*)d_in[0];
    const float* w1  = (const float*)d_in[1];
    const float* w2  = (const float*)d_in[2];
    const float* ga1 = (const float*)d_in[3];
    const float* be1 = (const float*)d_in[4];
    const float* ga2 = (const float*)d_in[5];
    const float* be2 = (const float*)d_in[6];
    float* out = (float*)d_out;

    char *xb1, *xb2, *U, *V1, *V2;
    float *xT, *y2, *s1, *bi1, *s2, *bi2;
    short* y1;
    cudaGetSymbolAddress((void**)&xb1, g_xb1);
    cudaGetSymbolAddress((void**)&xb2, g_xb2);
    cudaGetSymbolAddress((void**)&U,   g_U);
    cudaGetSymbolAddress((void**)&V1,  g_V1);
    cudaGetSymbolAddress((void**)&V2,  g_V2);
    cudaGetSymbolAddress((void**)&xT,  g_xT);
    cudaGetSymbolAddress((void**)&y1,  g_y1);
    cudaGetSymbolAddress((void**)&y2,  g_y2);
    cudaGetSymbolAddress((void**)&s1,  g_s1);
    cudaGetSymbolAddress((void**)&bi1, g_bi1);
    cudaGetSymbolAddress((void**)&s2,  g_s2);
    cudaGetSymbolAddress((void**)&bi2, g_bi2);

    cudaFuncSetAttribute(wino_gemm<false>,
                         cudaFuncAttributeMaxDynamicSharedMemorySize, GEMM_SMEM);
    cudaFuncSetAttribute(wino_gemm<true>,
                         cudaFuncAttributeMaxDynamicSharedMemorySize, GEMM_SMEM);

    prep_x_kernel<<<dim3(25, 8, 64), dim3(32, 8)>>>(x, xb1, xT);
    wino_v_kernel<<<256, 256>>>(w1, V1);
    wino_v_kernel<<<256, 256>>>(w2, V2);

    wino_u_kernel<<<MWIN * 32 / 256, 256>>>(xb1, U);
    wino_gemm<false><<<dim3(196, 4), 256, GEMM_SMEM>>>(U, V1, nullptr, (void*)y1);
    stats_kernel<short><<<256, 256>>>(y1, ga1, be1, s1, bi1);
    binarize_kernel<<<dim3(1568, 8), dim3(32, 8)>>>(y1, s1, bi1, xb2);

    wino_u_kernel<<<MWIN * 32 / 256, 256>>>(xb2, U);
    wino_gemm<true><<<dim3(196, 4), 256, GEMM_SMEM>>>(U, V2, xT, (void*)y2);
    stats_kernel<float><<<256, 256>>>(y2, ga2, be2, s2, bi2);
    final_kernel<<<1184, 256>>>(y2, s2, bi2, out);
}

// round 11
// speedup vs baseline: 1.5206x; 1.5206x over previous
#include <cuda_runtime.h>
#include <cstdint>

#define NIMG 64
#define CCH  256
#define HH28 28
#define HWSZ 784
#define NHW  50176
#define NT2  196          // winograd tiles per image (14x14)
#define MWIN 12544        // 64*196 tile-rows
#define UPLANE (MWIN * CCH)   // bytes per U[t] plane (int8)
#define VPLANE (CCH * CCH)
#define NSLICE 8
#define SLICELEN (NHW / NSLICE)

// wino gemm smem: 2 stages, each A(64 x 80B) + B(64 x 80B)
#define AROW 80
#define HALF_BYTES (64 * AROW)
#define STAGE (2 * HALF_BYTES)

// ---------------------------------------------------------------- helpers
__device__ __forceinline__ uint32_t smem_u32(const void* p) {
    uint32_t a;
    asm("{ .reg .u64 t; cvta.to.shared.u64 t, %1; cvt.u32.u64 %0, t; }" : "=r"(a) : "l"(p));
    return a;
}
__device__ __forceinline__ void cpa16(uint32_t dst, const void* src) {
    asm volatile("cp.async.cg.shared.global [%0], [%1], 16;"
                 :: "r"(dst), "l"(src) : "memory");
}
__device__ __forceinline__ void mma_s8(int* d, const uint32_t* a, const uint32_t* b) {
    asm volatile(
        "mma.sync.aligned.m16n8k32.row.col.s32.s8.s8.s32 "
        "{%0,%1,%2,%3}, {%4,%5,%6,%7}, {%8,%9}, {%0,%1,%2,%3};"
        : "+r"(d[0]), "+r"(d[1]), "+r"(d[2]), "+r"(d[3])
        : "r"(a[0]), "r"(a[1]), "r"(a[2]), "r"(a[3]), "r"(b[0]), "r"(b[1]));
}

// ---------------------------------------------------------------- scratch
__device__ __align__(256) char  g_xb1[(size_t)NHW * CCH];   // binarized x, NHWC int8
__device__ __align__(256) char  g_xb2[(size_t)NHW * CCH];   // binarized BN1 out, NHWC int8
__device__ __align__(256) char  g_U[(size_t)16 * UPLANE];   // winograd input transform
__device__ __align__(256) char  g_V1[16 * VPLANE];          // winograd weight transform
__device__ __align__(256) char  g_V2[16 * VPLANE];
__device__ short g_y1[(size_t)CCH * NHW];                   // conv1 out, col-major
__device__ float g_y2[(size_t)CCH * NHW];                   // conv2+resid, col-major
__device__ float g_ps[CCH * NSLICE], g_pq[CCH * NSLICE];    // stats partials
__device__ float g_s1[CCH], g_bi1[CCH], g_s2[CCH], g_bi2[CCH];

// -------- K1: binarize x -> NHWC int8 (transpose NCHW -> NHWC)
__global__ void prep_x_kernel(const float* __restrict__ x,
                              char* __restrict__ xb1) {
    __shared__ float t[32][33];
    int tx = threadIdx.x, ty = threadIdx.y;
    int n  = blockIdx.z;
    int c0 = blockIdx.y * 32;
    int p0 = blockIdx.x * 32;
    #pragma unroll
    for (int j = 0; j < 4; j++) {
        int c = c0 + ty + j * 8;
        int p = p0 + tx;
        float v = 0.f;
        if (p < HWSZ) v = x[((size_t)n * CCH + c) * HWSZ + p];
        t[ty + j * 8][tx] = v;
    }
    __syncthreads();
    #pragma unroll
    for (int j = 0; j < 4; j++) {
        int p = p0 + ty + j * 8;
        if (p < HWSZ) {
            float v = t[tx][ty + j * 8];
            xb1[((size_t)(n * HWSZ + p)) * CCH + c0 + tx] = (v >= 0.f) ? 1 : -1;
        }
    }
}

// -------- wino V: w (OIHW f32) -> V[t][cout*256+cin] int8, V = (2G) sign(w) (2G)^T
__global__ void wino_v_kernel(const float* __restrict__ w, char* __restrict__ V) {
    int idx = blockIdx.x * 256 + threadIdx.x;   // cout*256 + cin
    const float* p = w + (size_t)idx * 9;
    int b[3][3];
    #pragma unroll
    for (int i = 0; i < 3; i++)
        #pragma unroll
        for (int j = 0; j < 3; j++)
            b[i][j] = (p[i * 3 + j] >= 0.f) ? 1 : -1;
    int g[4][3];
    #pragma unroll
    for (int j = 0; j < 3; j++) {
        g[0][j] = 2 * b[0][j];
        g[1][j] = b[0][j] + b[1][j] + b[2][j];
        g[2][j] = b[0][j] - b[1][j] + b[2][j];
        g[3][j] = 2 * b[2][j];
    }
    #pragma unroll
    for (int i = 0; i < 4; i++) {
        int v0 = 2 * g[i][0];
        int v1 = g[i][0] + g[i][1] + g[i][2];
        int v2 = g[i][0] - g[i][1] + g[i][2];
        int v3 = 2 * g[i][2];
        V[(size_t)(i * 4 + 0) * VPLANE + idx] = (char)v0;
        V[(size_t)(i * 4 + 1) * VPLANE + idx] = (char)v1;
        V[(size_t)(i * 4 + 2) * VPLANE + idx] = (char)v2;
        V[(size_t)(i * 4 + 3) * VPLANE + idx] = (char)v3;
    }
}

// -------- wino U: xb NHWC int8 -> U[t][tile*256+c] int8  (B^T d B, |U|<=4)
__global__ void wino_u_kernel(const char* __restrict__ xb, char* __restrict__ U) {
    int item = blockIdx.x * 256 + threadIdx.x;   // tile*64 + cgroup
    int tile = item >> 6;
    int cg = item & 63;                          // 4 channels per thread
    int n = tile / NT2;
    int rt = tile - n * NT2;
    int ty = rt / 14, tx = rt - ty * 14;
    int h0 = 2 * ty - 1, w0 = 2 * tx - 1;
    const char* base = xb + ((size_t)n * HWSZ) * CCH + cg * 4;

    uint32_t d[4][4];
    #pragma unroll
    for (int i = 0; i < 4; i++) {
        int h = h0 + i;
        #pragma unroll
        for (int j = 0; j < 4; j++) {
            int w = w0 + j;
            d[i][j] = (((unsigned)h < 28u) & ((unsigned)w < 28u))
                ? *reinterpret_cast<const uint32_t*>(base + (size_t)(h * HH28 + w) * CCH)
                : 0u;
        }
    }
    uint32_t r[4][4];
    #pragma unroll
    for (int j = 0; j < 4; j++) {
        r[0][j] = __vsub4(d[0][j], d[2][j]);
        r[1][j] = __vadd4(d[1][j], d[2][j]);
        r[2][j] = __vsub4(d[2][j], d[1][j]);
        r[3][j] = __vsub4(d[1][j], d[3][j]);
    }
    #pragma unroll
    for (int i = 0; i < 4; i++) {
        uint32_t u0 = __vsub4(r[i][0], r[i][2]);
        uint32_t u1 = __vadd4(r[i][1], r[i][2]);
        uint32_t u2 = __vsub4(r[i][2], r[i][1]);
        uint32_t u3 = __vsub4(r[i][1], r[i][3]);
        size_t off = (size_t)tile * CCH + cg * 4;
        *reinterpret_cast<uint32_t*>(U + (size_t)(i * 4 + 0) * UPLANE + off) = u0;
        *reinterpret_cast<uint32_t*>(U + (size_t)(i * 4 + 1) * UPLANE + off) = u1;
        *reinterpret_cast<uint32_t*>(U + (size_t)(i * 4 + 2) * UPLANE + off) = u2;
        *reinterpret_cast<uint32_t*>(U + (size_t)(i * 4 + 3) * UPLANE + off) = u3;
    }
}

// -------- wino GEMM: for t in 0..15: Mhat = U[t]*V[t]^T, fold into Y, write col-major
// grid (196, 4): x = M tile (64 wino rows), y = cout tile (64)
// RESID: residual read directly from x (NCHW fp32)
template <bool RESID>
__global__ void __launch_bounds__(256, 2)
wino_gemm(const char* __restrict__ U,
          const char* __restrict__ V,
          const float* __restrict__ xres,
          void* __restrict__ outp) {
    __shared__ __align__(16) char sm[2][STAGE];

    int tid = threadIdx.x, wid = tid >> 5, lane = tid & 31;
    int g = lane >> 2, tg = lane & 3;
    int warpM = wid & 3, warpN = wid >> 2;    // 4 x 2 warps, warp tile 16x32

    int lrow = tid >> 2, lu = tid & 3;        // one 16B unit per thread per matrix
    const char* Ubase = U + ((size_t)blockIdx.x * 64 + lrow) * CCH + lu * 16;
    const char* Vbase = V + ((size_t)blockIdx.y * 64 + lrow) * CCH + lu * 16;
    uint32_t dstA = smem_u32(&sm[0][0]) + lrow * AROW + lu * 16;
    uint32_t dstB = dstA + HALF_BYTES;

    auto issue = [&](int chunk, int s) {
        int t = chunk >> 2, kc = chunk & 3;
        size_t koff = (size_t)t * UPLANE + kc * 64;
        cpa16(dstA + s * STAGE, Ubase + koff);
        cpa16(dstB + s * STAGE, Vbase + (size_t)t * VPLANE + kc * 64);
        asm volatile("cp.async.commit_group;" ::: "memory");
    };

    int Y[4][4][4];
    int acc[4][4];
    #pragma unroll
    for (int ni = 0; ni < 4; ni++)
        #pragma unroll
        for (int j = 0; j < 4; j++) {
            acc[ni][j] = 0;
            #pragma unroll
            for (int p = 0; p < 4; p++) Y[ni][j][p] = 0;
        }

    issue(0, 0);
    #pragma unroll 1
    for (int chunk = 0; chunk < 64; ++chunk) {
        int s = chunk & 1;
        if (chunk + 1 < 64) {
            issue(chunk + 1, s ^ 1);
            asm volatile("cp.async.wait_group 1;" ::: "memory");
        } else {
            asm volatile("cp.async.wait_group 0;" ::: "memory");
        }
        __syncthreads();

        const char* As = sm[s];
        const char* Bs = sm[s] + HALF_BYTES;
        #pragma unroll
        for (int ks = 0; ks < 2; ks++) {
            int ko = ks * 32;
            uint32_t a[4], b[4][2];
            {
                int r = warpM * 16 + g;
                a[0] = *reinterpret_cast<const uint32_t*>(As + r * AROW + ko + tg * 4);
                a[1] = *reinterpret_cast<const uint32_t*>(As + (r + 8) * AROW + ko + tg * 4);
                a[2] = *reinterpret_cast<const uint32_t*>(As + r * AROW + ko + 16 + tg * 4);
                a[3] = *reinterpret_cast<const uint32_t*>(As + (r + 8) * AROW + ko + 16 + tg * 4);
            }
            #pragma unroll
            for (int ni = 0; ni < 4; ni++) {
                int c = warpN * 32 + ni * 8 + g;
                b[ni][0] = *reinterpret_cast<const uint32_t*>(Bs + c * AROW + ko + tg * 4);
                b[ni][1] = *reinterpret_cast<const uint32_t*>(Bs + c * AROW + ko + 16 + tg * 4);
            }
            #pragma unroll
            for (int ni = 0; ni < 4; ni++)
                mma_s8(acc[ni], a, b[ni]);
        }
        __syncthreads();

        if ((chunk & 3) == 3) {
            // fold Mhat (acc) of t = chunk>>2 into Y, reset acc
            int t = chunk >> 2;
            int tr = t >> 2, tc = t & 3;
            int cr0 = (tr <= 2) ? 1 : 0;
            int cr1 = (tr == 0) ? 0 : ((tr == 1) ? 1 : -1);
            int cc0 = (tc <= 2) ? 1 : 0;
            int cc1 = (tc == 0) ? 0 : ((tc == 1) ? 1 : -1);
            #pragma unroll
            for (int ni = 0; ni < 4; ni++)
                #pragma unroll
                for (int j = 0; j < 4; j++) {
                    int v = acc[ni][j];
                    Y[ni][j][0] += cr0 * cc0 * v;
                    Y[ni][j][1] += cr0 * cc1 * v;
                    Y[ni][j][2] += cr1 * cc0 * v;
                    Y[ni][j][3] += cr1 * cc1 * v;
                    acc[ni][j] = 0;
                }
        }
    }

    // epilogue: each Mhat element -> 2x2 output pixels, col-major [c][m]
    #pragma unroll
    for (int j = 0; j < 4; j++) {
        int mp = blockIdx.x * 64 + warpM * 16 + g + 8 * (j >> 1);  // wino row
        int n = mp / NT2;
        int rt = mp - n * NT2;
        int ty = rt / 14, tx = rt - ty * 14;
        int hwbase = (2 * ty) * HH28 + 2 * tx;
        int mbase = n * HWSZ + hwbase;
        #pragma unroll
        for (int ni = 0; ni < 4; ni++) {
            int c = blockIdx.y * 64 + warpN * 32 + ni * 8 + 2 * tg + (j & 1);
            size_t obase = (size_t)c * NHW + mbase;
            size_t rbase = ((size_t)n * CCH + c) * HWSZ + hwbase;
            #pragma unroll
            for (int p = 0; p < 4; p++) {
                size_t off = (p >> 1) * HH28 + (p & 1);
                int val = Y[ni][j][p] >> 2;   // exact /4
                if (RESID) {
                    reinterpret_cast<float*>(outp)[obase + off] = (float)val + xres[rbase + off];
                } else {
                    reinterpret_cast<short*>(outp)[obase + off] = (short)val;
                }
            }
        }
    }
}

// -------- stats partials: grid (256, NSLICE), block 256
template <typename T>
__global__ void stats_part(const T* __restrict__ ycm,
                           float* __restrict__ ps, float* __restrict__ pq) {
    int c = blockIdx.x, sl = blockIdx.y;
    const T* p = ycm + (size_t)c * NHW + sl * SLICELEN;
    float s = 0.f, q = 0.f;
    for (int i = threadIdx.x; i < SLICELEN; i += 256) {
        float v = (float)p[i];
        s += v; q += v * v;
    }
    __shared__ float rs[256], rq[256];
    rs[threadIdx.x] = s; rq[threadIdx.x] = q;
    __syncthreads();
    for (int o = 128; o > 0; o >>= 1) {
        if (threadIdx.x < o) { rs[threadIdx.x] += rs[threadIdx.x + o]; rq[threadIdx.x] += rq[threadIdx.x + o]; }
        __syncthreads();
    }
    if (threadIdx.x == 0) { ps[c * NSLICE + sl] = rs[0]; pq[c * NSLICE + sl] = rq[0]; }
}

// -------- stats finalize: 1 block, 256 threads (one channel each)
__global__ void stats_fin(const float* __restrict__ ps, const float* __restrict__ pq,
                          const float* __restrict__ gamma, const float* __restrict__ beta,
                          float* __restrict__ scl, float* __restrict__ bia) {
    int c = threadIdx.x;
    float s = 0.f, q = 0.f;
    #pragma unroll
    for (int j = 0; j < NSLICE; j++) { s += ps[c * NSLICE + j]; q += pq[c * NSLICE + j]; }
    float mean = s / (float)NHW;
    float var  = q / (float)NHW - mean * mean;
    float inv  = rsqrtf(var + 1e-5f);
    float sc   = gamma[c] * inv;
    scl[c] = sc;
    bia[c] = beta[c] - mean * sc;
}

// -------- binarize BN1 output: [c][m] int16 -> [m][c] int8 +-1
__global__ void binarize_kernel(const short* __restrict__ ycm,
                                const float* __restrict__ scl, const float* __restrict__ bia,
                                char* __restrict__ xb2) {
    __shared__ short t[32][33];
    __shared__ float sc[32], bi[32];
    int tx = threadIdx.x, ty = threadIdx.y;
    int c0 = blockIdx.y * 32, m0 = blockIdx.x * 32;
    if (ty == 0) { sc[tx] = scl[c0 + tx]; bi[tx] = bia[c0 + tx]; }
    #pragma unroll
    for (int j = 0; j < 4; j++) {
        int c = c0 + ty + j * 8;
        t[ty + j * 8][tx] = ycm[(size_t)c * NHW + m0 + tx];
    }
    __syncthreads();
    #pragma unroll
    for (int j = 0; j < 4; j++) {
        int m = m0 + ty + j * 8;
        float v = (float)t[tx][ty + j * 8] * sc[tx] + bi[tx];
        xb2[(size_t)m * CCH + c0 + tx] = (v >= 0.f) ? 1 : -1;
    }
}

// -------- final: BN2 + hardtanh + NCHW
__global__ void final_kernel(const float* __restrict__ y2,
                             const float* __restrict__ scl, const float* __restrict__ bia,
                             float* __restrict__ out) {
    size_t total = (size_t)CCH * NHW;
    for (size_t idx = (size_t)blockIdx.x * blockDim.x + threadIdx.x; idx < total;
         idx += (size_t)gridDim.x * blockDim.x) {
        unsigned c = (unsigned)(idx / NHW);
        unsigned r = (unsigned)(idx - (size_t)c * NHW);
        unsigned n = r / HWSZ;
        unsigned hw = r - n * HWSZ;
        float v = y2[idx] * scl[c] + bia[c];
        v = fminf(fmaxf(v, -1.f), 1.f);
        out[((size_t)n * CCH + c) * HWSZ + hw] = v;
    }
}

// ---------------------------------------------------------------- launcher
extern "C" void kernel_launch(void* const* d_in, const int* in_sizes, int n_in,
                              void* d_out, int out_size) {
    const float* x   = (const float*)d_in[0];
    const float* w1  = (const float*)d_in[1];
    const float* w2  = (const float*)d_in[2];
    const float* ga1 = (const float*)d_in[3];
    const float* be1 = (const float*)d_in[4];
    const float* ga2 = (const float*)d_in[5];
    const float* be2 = (const float*)d_in[6];
    float* out = (float*)d_out;

    char *xb1, *xb2, *U, *V1, *V2;
    float *y2, *ps, *pq, *s1, *bi1, *s2, *bi2;
    short* y1;
    cudaGetSymbolAddress((void**)&xb1, g_xb1);
    cudaGetSymbolAddress((void**)&xb2, g_xb2);
    cudaGetSymbolAddress((void**)&U,   g_U);
    cudaGetSymbolAddress((void**)&V1,  g_V1);
    cudaGetSymbolAddress((void**)&V2,  g_V2);
    cudaGetSymbolAddress((void**)&y1,  g_y1);
    cudaGetSymbolAddress((void**)&y2,  g_y2);
    cudaGetSymbolAddress((void**)&ps,  g_ps);
    cudaGetSymbolAddress((void**)&pq,  g_pq);
    cudaGetSymbolAddress((void**)&s1,  g_s1);
    cudaGetSymbolAddress((void**)&bi1, g_bi1);
    cudaGetSymbolAddress((void**)&s2,  g_s2);
    cudaGetSymbolAddress((void**)&bi2, g_bi2);

    prep_x_kernel<<<dim3(25, 8, 64), dim3(32, 8)>>>(x, xb1);
    wino_v_kernel<<<256, 256>>>(w1, V1);
    wino_v_kernel<<<256, 256>>>(w2, V2);

    wino_u_kernel<<<MWIN * 64 / 256, 256>>>(xb1, U);
    wino_gemm<false><<<dim3(196, 4), 256>>>(U, V1, nullptr, (void*)y1);
    stats_part<short><<<dim3(256, NSLICE), 256>>>(y1, ps, pq);
    stats_fin<<<1, 256>>>(ps, pq, ga1, be1, s1, bi1);
    binarize_kernel<<<dim3(1568, 8), dim3(32, 8)>>>(y1, s1, bi1, xb2);

    wino_u_kernel<<<MWIN * 64 / 256, 256>>>(xb2, U);
    wino_gemm<true><<<dim3(196, 4), 256>>>(U, V2, x, (void*)y2);
    stats_part<float><<<dim3(256, NSLICE), 256>>>(y2, ps, pq);
    stats_fin<<<1, 256>>>(ps, pq, ga2, be2, s2, bi2);
    final_kernel<<<1184, 256>>>(y2, s2, bi2, out);
}

// round 12
// speedup vs baseline: 1.5496x; 1.0190x over previous
#include <cuda_runtime.h>
#include <cstdint>

#define NIMG 64
#define CCH  256
#define HH28 28
#define HWSZ 784
#define NHW  50176
#define NT2  196          // winograd tiles per image (14x14)
#define MWIN 12544        // 64*196 tile-rows
#define UPLANE (MWIN * CCH)   // bytes per U[t] plane (int8)
#define VPLANE (CCH * CCH)
#define NSLICE 8
#define SLICELEN (NHW / NSLICE)

// wino gemm smem: 3 stages, each A(64 x 80B) + B(64 x 80B)
#define AROW 80
#define HALF_BYTES (64 * AROW)
#define STAGE (2 * HALF_BYTES)

// ---------------------------------------------------------------- helpers
__device__ __forceinline__ uint32_t smem_u32(const void* p) {
    uint32_t a;
    asm("{ .reg .u64 t; cvta.to.shared.u64 t, %1; cvt.u32.u64 %0, t; }" : "=r"(a) : "l"(p));
    return a;
}
__device__ __forceinline__ void cpa16(uint32_t dst, const void* src) {
    asm volatile("cp.async.cg.shared.global [%0], [%1], 16;"
                 :: "r"(dst), "l"(src) : "memory");
}
__device__ __forceinline__ void mma_s8(int* d, const uint32_t* a, const uint32_t* b) {
    asm volatile(
        "mma.sync.aligned.m16n8k32.row.col.s32.s8.s8.s32 "
        "{%0,%1,%2,%3}, {%4,%5,%6,%7}, {%8,%9}, {%0,%1,%2,%3};"
        : "+r"(d[0]), "+r"(d[1]), "+r"(d[2]), "+r"(d[3])
        : "r"(a[0]), "r"(a[1]), "r"(a[2]), "r"(a[3]), "r"(b[0]), "r"(b[1]));
}

// ---------------------------------------------------------------- scratch
__device__ __align__(256) char  g_xb1[(size_t)NHW * CCH];   // binarized x, NHWC int8
__device__ __align__(256) char  g_xb2[(size_t)NHW * CCH];   // binarized BN1 out, NHWC int8
__device__ __align__(256) char  g_U[(size_t)16 * UPLANE];   // winograd input transform
__device__ __align__(256) char  g_V1[16 * VPLANE];          // winograd weight transform
__device__ __align__(256) char  g_V2[16 * VPLANE];
__device__ short g_y1[(size_t)CCH * NHW];                   // conv1 out, col-major
__device__ float g_y2[(size_t)CCH * NHW];                   // conv2+resid, col-major
__device__ float g_ps[CCH * NSLICE], g_pq[CCH * NSLICE];    // stats partials
__device__ float g_s1[CCH], g_bi1[CCH], g_s2[CCH], g_bi2[CCH];

// -------- K1: binarize x -> NHWC int8 (transpose NCHW -> NHWC)
__global__ void prep_x_kernel(const float* __restrict__ x,
                              char* __restrict__ xb1) {
    __shared__ float t[32][33];
    int tx = threadIdx.x, ty = threadIdx.y;
    int n  = blockIdx.z;
    int c0 = blockIdx.y * 32;
    int p0 = blockIdx.x * 32;
    #pragma unroll
    for (int j = 0; j < 4; j++) {
        int c = c0 + ty + j * 8;
        int p = p0 + tx;
        float v = 0.f;
        if (p < HWSZ) v = x[((size_t)n * CCH + c) * HWSZ + p];
        t[ty + j * 8][tx] = v;
    }
    __syncthreads();
    #pragma unroll
    for (int j = 0; j < 4; j++) {
        int p = p0 + ty + j * 8;
        if (p < HWSZ) {
            float v = t[tx][ty + j * 8];
            xb1[((size_t)(n * HWSZ + p)) * CCH + c0 + tx] = (v >= 0.f) ? 1 : -1;
        }
    }
}

// -------- wino V: w (OIHW f32) -> V[t][cout*256+cin] int8, V = (2G) sign(w) (2G)^T
__global__ void wino_v_kernel(const float* __restrict__ w, char* __restrict__ V) {
    int idx = blockIdx.x * 256 + threadIdx.x;   // cout*256 + cin
    const float* p = w + (size_t)idx * 9;
    int b[3][3];
    #pragma unroll
    for (int i = 0; i < 3; i++)
        #pragma unroll
        for (int j = 0; j < 3; j++)
            b[i][j] = (p[i * 3 + j] >= 0.f) ? 1 : -1;
    int g[4][3];
    #pragma unroll
    for (int j = 0; j < 3; j++) {
        g[0][j] = 2 * b[0][j];
        g[1][j] = b[0][j] + b[1][j] + b[2][j];
        g[2][j] = b[0][j] - b[1][j] + b[2][j];
        g[3][j] = 2 * b[2][j];
    }
    #pragma unroll
    for (int i = 0; i < 4; i++) {
        int v0 = 2 * g[i][0];
        int v1 = g[i][0] + g[i][1] + g[i][2];
        int v2 = g[i][0] - g[i][1] + g[i][2];
        int v3 = 2 * g[i][2];
        V[(size_t)(i * 4 + 0) * VPLANE + idx] = (char)v0;
        V[(size_t)(i * 4 + 1) * VPLANE + idx] = (char)v1;
        V[(size_t)(i * 4 + 2) * VPLANE + idx] = (char)v2;
        V[(size_t)(i * 4 + 3) * VPLANE + idx] = (char)v3;
    }
}

// -------- wino U: xb NHWC int8 -> U[t][tile*256+c] int8  (B^T d B, |U|<=4)
__global__ void wino_u_kernel(const char* __restrict__ xb, char* __restrict__ U) {
    int item = blockIdx.x * 256 + threadIdx.x;   // tile*64 + cgroup
    int tile = item >> 6;
    int cg = item & 63;                          // 4 channels per thread
    int n = tile / NT2;
    int rt = tile - n * NT2;
    int ty = rt / 14, tx = rt - ty * 14;
    int h0 = 2 * ty - 1, w0 = 2 * tx - 1;
    const char* base = xb + ((size_t)n * HWSZ) * CCH + cg * 4;

    uint32_t d[4][4];
    #pragma unroll
    for (int i = 0; i < 4; i++) {
        int h = h0 + i;
        #pragma unroll
        for (int j = 0; j < 4; j++) {
            int w = w0 + j;
            d[i][j] = (((unsigned)h < 28u) & ((unsigned)w < 28u))
                ? *reinterpret_cast<const uint32_t*>(base + (size_t)(h * HH28 + w) * CCH)
                : 0u;
        }
    }
    uint32_t r[4][4];
    #pragma unroll
    for (int j = 0; j < 4; j++) {
        r[0][j] = __vsub4(d[0][j], d[2][j]);
        r[1][j] = __vadd4(d[1][j], d[2][j]);
        r[2][j] = __vsub4(d[2][j], d[1][j]);
        r[3][j] = __vsub4(d[1][j], d[3][j]);
    }
    #pragma unroll
    for (int i = 0; i < 4; i++) {
        uint32_t u0 = __vsub4(r[i][0], r[i][2]);
        uint32_t u1 = __vadd4(r[i][1], r[i][2]);
        uint32_t u2 = __vsub4(r[i][2], r[i][1]);
        uint32_t u3 = __vsub4(r[i][1], r[i][3]);
        size_t off = (size_t)tile * CCH + cg * 4;
        *reinterpret_cast<uint32_t*>(U + (size_t)(i * 4 + 0) * UPLANE + off) = u0;
        *reinterpret_cast<uint32_t*>(U + (size_t)(i * 4 + 1) * UPLANE + off) = u1;
        *reinterpret_cast<uint32_t*>(U + (size_t)(i * 4 + 2) * UPLANE + off) = u2;
        *reinterpret_cast<uint32_t*>(U + (size_t)(i * 4 + 3) * UPLANE + off) = u3;
    }
}

// -------- wino GEMM: for t in 0..15: Mhat = U[t]*V[t]^T, fold into Y, write col-major
// grid (196, 4); 3-stage cp.async ring, one __syncthreads per chunk
template <bool RESID>
__global__ void __launch_bounds__(256, 2)
wino_gemm(const char* __restrict__ U,
          const char* __restrict__ V,
          const float* __restrict__ xres,
          void* __restrict__ outp) {
    __shared__ __align__(16) char sm[3][STAGE];

    int tid = threadIdx.x, wid = tid >> 5, lane = tid & 31;
    int g = lane >> 2, tg = lane & 3;
    int warpM = wid & 3, warpN = wid >> 2;    // 4 x 2 warps, warp tile 16x32

    int lrow = tid >> 2, lu = tid & 3;        // one 16B unit per thread per matrix
    const char* Ubase = U + ((size_t)blockIdx.x * 64 + lrow) * CCH + lu * 16;
    const char* Vbase = V + ((size_t)blockIdx.y * 64 + lrow) * CCH + lu * 16;
    uint32_t dstA = smem_u32(&sm[0][0]) + lrow * AROW + lu * 16;
    uint32_t dstB = dstA + HALF_BYTES;

    auto issue = [&](int chunk, int s) {
        int t = chunk >> 2, kc = chunk & 3;
        size_t koff = (size_t)t * UPLANE + kc * 64;
        cpa16(dstA + s * STAGE, Ubase + koff);
        cpa16(dstB + s * STAGE, Vbase + (size_t)t * VPLANE + kc * 64);
        asm volatile("cp.async.commit_group;" ::: "memory");
    };

    int Y[4][4][4];
    int acc[4][4];
    #pragma unroll
    for (int ni = 0; ni < 4; ni++)
        #pragma unroll
        for (int j = 0; j < 4; j++) {
            acc[ni][j] = 0;
            #pragma unroll
            for (int p = 0; p < 4; p++) Y[ni][j][p] = 0;
        }

    issue(0, 0);
    issue(1, 1);
    int s = 0, s2 = 2;    // s = stage of current chunk, s2 = stage for chunk+2
    #pragma unroll 1
    for (int chunk = 0; chunk < 64; ++chunk) {
        if (chunk < 63) {
            asm volatile("cp.async.wait_group 1;" ::: "memory");
        } else {
            asm volatile("cp.async.wait_group 0;" ::: "memory");
        }
        __syncthreads();
        if (chunk + 2 < 64) issue(chunk + 2, s2);

        const char* As = sm[s];
        const char* Bs = sm[s] + HALF_BYTES;
        #pragma unroll
        for (int ks = 0; ks < 2; ks++) {
            int ko = ks * 32;
            uint32_t a[4], b[4][2];
            {
                int r = warpM * 16 + g;
                a[0] = *reinterpret_cast<const uint32_t*>(As + r * AROW + ko + tg * 4);
                a[1] = *reinterpret_cast<const uint32_t*>(As + (r + 8) * AROW + ko + tg * 4);
                a[2] = *reinterpret_cast<const uint32_t*>(As + r * AROW + ko + 16 + tg * 4);
                a[3] = *reinterpret_cast<const uint32_t*>(As + (r + 8) * AROW + ko + 16 + tg * 4);
            }
            #pragma unroll
            for (int ni = 0; ni < 4; ni++) {
                int c = warpN * 32 + ni * 8 + g;
                b[ni][0] = *reinterpret_cast<const uint32_t*>(Bs + c * AROW + ko + tg * 4);
                b[ni][1] = *reinterpret_cast<const uint32_t*>(Bs + c * AROW + ko + 16 + tg * 4);
            }
            #pragma unroll
            for (int ni = 0; ni < 4; ni++)
                mma_s8(acc[ni], a, b[ni]);
        }

        if ((chunk & 3) == 3) {
            // fold Mhat (acc) of t = chunk>>2 into Y, reset acc
            int t = chunk >> 2;
            int tr = t >> 2, tc = t & 3;
            int cr0 = (tr <= 2) ? 1 : 0;
            int cr1 = (tr == 0) ? 0 : ((tr == 1) ? 1 : -1);
            int cc0 = (tc <= 2) ? 1 : 0;
            int cc1 = (tc == 0) ? 0 : ((tc == 1) ? 1 : -1);
            #pragma unroll
            for (int ni = 0; ni < 4; ni++)
                #pragma unroll
                for (int j = 0; j < 4; j++) {
                    int v = acc[ni][j];
                    Y[ni][j][0] += cr0 * cc0 * v;
                    Y[ni][j][1] += cr0 * cc1 * v;
                    Y[ni][j][2] += cr1 * cc0 * v;
                    Y[ni][j][3] += cr1 * cc1 * v;
                    acc[ni][j] = 0;
                }
        }
        s = (s == 2) ? 0 : s + 1;
        s2 = (s2 == 2) ? 0 : s2 + 1;
    }

    // epilogue: each Mhat element -> 2x2 output pixels, col-major [c][m]
    #pragma unroll
    for (int j = 0; j < 4; j++) {
        int mp = blockIdx.x * 64 + warpM * 16 + g + 8 * (j >> 1);  // wino row
        int n = mp / NT2;
        int rt = mp - n * NT2;
        int ty = rt / 14, tx = rt - ty * 14;
        int hwbase = (2 * ty) * HH28 + 2 * tx;
        int mbase = n * HWSZ + hwbase;
        #pragma unroll
        for (int ni = 0; ni < 4; ni++) {
            int c = blockIdx.y * 64 + warpN * 32 + ni * 8 + 2 * tg + (j & 1);
            size_t obase = (size_t)c * NHW + mbase;
            size_t rbase = ((size_t)n * CCH + c) * HWSZ + hwbase;
            #pragma unroll
            for (int p = 0; p < 4; p++) {
                size_t off = (p >> 1) * HH28 + (p & 1);
                int val = Y[ni][j][p] >> 2;   // exact /4
                if (RESID) {
                    reinterpret_cast<float*>(outp)[obase + off] = (float)val + xres[rbase + off];
                } else {
                    reinterpret_cast<short*>(outp)[obase + off] = (short)val;
                }
            }
        }
    }
}

// -------- stats partials: grid (256, NSLICE), block 256
template <typename T>
__global__ void stats_part(const T* __restrict__ ycm,
                           float* __restrict__ ps, float* __restrict__ pq) {
    int c = blockIdx.x, sl = blockIdx.y;
    const T* p = ycm + (size_t)c * NHW + sl * SLICELEN;
    float s = 0.f, q = 0.f;
    for (int i = threadIdx.x; i < SLICELEN; i += 256) {
        float v = (float)p[i];
        s += v; q += v * v;
    }
    __shared__ float rs[256], rq[256];
    rs[threadIdx.x] = s; rq[threadIdx.x] = q;
    __syncthreads();
    for (int o = 128; o > 0; o >>= 1) {
        if (threadIdx.x < o) { rs[threadIdx.x] += rs[threadIdx.x + o]; rq[threadIdx.x] += rq[threadIdx.x + o]; }
        __syncthreads();
    }
    if (threadIdx.x == 0) { ps[c * NSLICE + sl] = rs[0]; pq[c * NSLICE + sl] = rq[0]; }
}

// -------- stats finalize: 1 block, 256 threads (one channel each)
__global__ void stats_fin(const float* __restrict__ ps, const float* __restrict__ pq,
                          const float* __restrict__ gamma, const float* __restrict__ beta,
                          float* __restrict__ scl, float* __restrict__ bia) {
    int c = threadIdx.x;
    float s = 0.f, q = 0.f;
    #pragma unroll
    for (int j = 0; j < NSLICE; j++) { s += ps[c * NSLICE + j]; q += pq[c * NSLICE + j]; }
    float mean = s / (float)NHW;
    float var  = q / (float)NHW - mean * mean;
    float inv  = rsqrtf(var + 1e-5f);
    float sc   = gamma[c] * inv;
    scl[c] = sc;
    bia[c] = beta[c] - mean * sc;
}

// -------- binarize BN1 output: [c][m] int16 -> [m][c] int8 +-1
__global__ void binarize_kernel(const short* __restrict__ ycm,
                                const float* __restrict__ scl, const float* __restrict__ bia,
                                char* __restrict__ xb2) {
    __shared__ short t[32][33];
    __shared__ float sc[32], bi[32];
    int tx = threadIdx.x, ty = threadIdx.y;
    int c0 = blockIdx.y * 32, m0 = blockIdx.x * 32;
    if (ty == 0) { sc[tx] = scl[c0 + tx]; bi[tx] = bia[c0 + tx]; }
    #pragma unroll
    for (int j = 0; j < 4; j++) {
        int c = c0 + ty + j * 8;
        t[ty + j * 8][tx] = ycm[(size_t)c * NHW + m0 + tx];
    }
    __syncthreads();
    #pragma unroll
    for (int j = 0; j < 4; j++) {
        int m = m0 + ty + j * 8;
        float v = (float)t[tx][ty + j * 8] * sc[tx] + bi[tx];
        xb2[(size_t)m * CCH + c0 + tx] = (v >= 0.f) ? 1 : -1;
    }
}

// -------- final: BN2 + hardtanh + NCHW
__global__ void final_kernel(const float* __restrict__ y2,
                             const float* __restrict__ scl, const float* __restrict__ bia,
                             float* __restrict__ out) {
    size_t total = (size_t)CCH * NHW;
    for (size_t idx = (size_t)blockIdx.x * blockDim.x + threadIdx.x; idx < total;
         idx += (size_t)gridDim.x * blockDim.x) {
        unsigned c = (unsigned)(idx / NHW);
        unsigned r = (unsigned)(idx - (size_t)c * NHW);
        unsigned n = r / HWSZ;
        unsigned hw = r - n * HWSZ;
        float v = y2[idx] * scl[c] + bia[c];
        v = fminf(fmaxf(v, -1.f), 1.f);
        out[((size_t)n * CCH + c) * HWSZ + hw] = v;
    }
}

// ---------------------------------------------------------------- launcher
extern "C" void kernel_launch(void* const* d_in, const int* in_sizes, int n_in,
                              void* d_out, int out_size) {
    const float* x   = (const float*)d_in[0];
    const float* w1  = (const float*)d_in[1];
    const float* w2  = (const float*)d_in[2];
    const float* ga1 = (const float*)d_in[3];
    const float* be1 = (const float*)d_in[4];
    const float* ga2 = (const float*)d_in[5];
    const float* be2 = (const float*)d_in[6];
    float* out = (float*)d_out;

    char *xb1, *xb2, *U, *V1, *V2;
    float *y2, *ps, *pq, *s1, *bi1, *s2, *bi2;
    short* y1;
    cudaGetSymbolAddress((void**)&xb1, g_xb1);
    cudaGetSymbolAddress((void**)&xb2, g_xb2);
    cudaGetSymbolAddress((void**)&U,   g_U);
    cudaGetSymbolAddress((void**)&V1,  g_V1);
    cudaGetSymbolAddress((void**)&V2,  g_V2);
    cudaGetSymbolAddress((void**)&y1,  g_y1);
    cudaGetSymbolAddress((void**)&y2,  g_y2);
    cudaGetSymbolAddress((void**)&ps,  g_ps);
    cudaGetSymbolAddress((void**)&pq,  g_pq);
    cudaGetSymbolAddress((void**)&s1,  g_s1);
    cudaGetSymbolAddress((void**)&bi1, g_bi1);
    cudaGetSymbolAddress((void**)&s2,  g_s2);
    cudaGetSymbolAddress((void**)&bi2, g_bi2);

    prep_x_kernel<<<dim3(25, 8, 64), dim3(32, 8)>>>(x, xb1);
    wino_v_kernel<<<256, 256>>>(w1, V1);
    wino_v_kernel<<<256, 256>>>(w2, V2);

    wino_u_kernel<<<MWIN * 64 / 256, 256>>>(xb1, U);
    wino_gemm<false><<<dim3(196, 4), 256>>>(U, V1, nullptr, (void*)y1);
    stats_part<short><<<dim3(256, NSLICE), 256>>>(y1, ps, pq);
    stats_fin<<<1, 256>>>(ps, pq, ga1, be1, s1, bi1);
    binarize_kernel<<<dim3(1568, 8), dim3(32, 8)>>>(y1, s1, bi1, xb2);

    wino_u_kernel<<<MWIN * 64 / 256, 256>>>(xb2, U);
    wino_gemm<true><<<dim3(196, 4), 256>>>(U, V2, x, (void*)y2);
    stats_part<float><<<dim3(256, NSLICE), 256>>>(y2, ps, pq);
    stats_fin<<<1, 256>>>(ps, pq, ga2, be2, s2, bi2);
    final_kernel<<<1184, 256>>>(y2, s2, bi2, out);
}

// round 14
// speedup vs baseline: 1.7323x; 1.1179x over previous
#include <cuda_runtime.h>
#include <cstdint>

#define NIMG 64
#define CCH  256
#define HH28 28
#define HWSZ 784
#define NHW  50176
#define NT2  196          // winograd tiles per image (14x14)
#define MWIN 12544        // 64*196 tile-rows
#define UPLANE (MWIN * CCH)   // bytes per U[t] plane (int8)
#define VPLANE (CCH * CCH)
#define NSLICE 8
#define SLICELEN (NHW / NSLICE)

// wino gemm smem: 3 stages, each A(32 x 80B) + B(64 x 80B)
#define AROW 80
#define A_HALF (32 * AROW)
#define B_HALF (64 * AROW)
#define STAGE (A_HALF + B_HALF)

// ---------------------------------------------------------------- helpers
__device__ __forceinline__ uint32_t smem_u32(const void* p) {
    uint32_t a;
    asm("{ .reg .u64 t; cvta.to.shared.u64 t, %1; cvt.u32.u64 %0, t; }" : "=r"(a) : "l"(p));
    return a;
}
__device__ __forceinline__ void cpa16(uint32_t dst, const void* src) {
    asm volatile("cp.async.cg.shared.global [%0], [%1], 16;"
                 :: "r"(dst), "l"(src) : "memory");
}
__device__ __forceinline__ void mma_s8(int* d, const uint32_t* a, const uint32_t* b) {
    asm volatile(
        "mma.sync.aligned.m16n8k32.row.col.s32.s8.s8.s32 "
        "{%0,%1,%2,%3}, {%4,%5,%6,%7}, {%8,%9}, {%0,%1,%2,%3};"
        : "+r"(d[0]), "+r"(d[1]), "+r"(d[2]), "+r"(d[3])
        : "r"(a[0]), "r"(a[1]), "r"(a[2]), "r"(a[3]), "r"(b[0]), "r"(b[1]));
}

// ---------------------------------------------------------------- scratch
__device__ __align__(256) char  g_xb1[(size_t)NHW * CCH];   // binarized x, NHWC int8
__device__ __align__(256) char  g_xb2[(size_t)NHW * CCH];   // binarized BN1 out, NHWC int8
__device__ __align__(256) char  g_U[(size_t)16 * UPLANE];   // winograd input transform
__device__ __align__(256) char  g_V1[16 * VPLANE];          // winograd weight transform
__device__ __align__(256) char  g_V2[16 * VPLANE];
__device__ short g_y1[(size_t)CCH * NHW];                   // conv1 out, col-major
__device__ float g_y2[(size_t)CCH * NHW];                   // conv2+resid, col-major
__device__ float g_ps[CCH * NSLICE], g_pq[CCH * NSLICE];    // stats partials
__device__ float g_s1[CCH], g_bi1[CCH], g_s2[CCH], g_bi2[CCH];

// -------- K1: binarize x -> NHWC int8 (transpose NCHW -> NHWC)
__global__ void prep_x_kernel(const float* __restrict__ x,
                              char* __restrict__ xb1) {
    __shared__ float t[32][33];
    int tx = threadIdx.x, ty = threadIdx.y;
    int n  = blockIdx.z;
    int c0 = blockIdx.y * 32;
    int p0 = blockIdx.x * 32;
    #pragma unroll
    for (int j = 0; j < 4; j++) {
        int c = c0 + ty + j * 8;
        int p = p0 + tx;
        float v = 0.f;
        if (p < HWSZ) v = x[((size_t)n * CCH + c) * HWSZ + p];
        t[ty + j * 8][tx] = v;
    }
    __syncthreads();
    #pragma unroll
    for (int j = 0; j < 4; j++) {
        int p = p0 + ty + j * 8;
        if (p < HWSZ) {
            float v = t[tx][ty + j * 8];
            xb1[((size_t)(n * HWSZ + p)) * CCH + c0 + tx] = (v >= 0.f) ? 1 : -1;
        }
    }
}

// -------- wino V: w (OIHW f32) -> V[t][cout*256+cin] int8, V = (2G) sign(w) (2G)^T
__global__ void wino_v_kernel(const float* __restrict__ w, char* __restrict__ V) {
    int idx = blockIdx.x * 256 + threadIdx.x;   // cout*256 + cin
    const float* p = w + (size_t)idx * 9;
    int b[3][3];
    #pragma unroll
    for (int i = 0; i < 3; i++)
        #pragma unroll
        for (int j = 0; j < 3; j++)
            b[i][j] = (p[i * 3 + j] >= 0.f) ? 1 : -1;
    int g[4][3];
    #pragma unroll
    for (int j = 0; j < 3; j++) {
        g[0][j] = 2 * b[0][j];
        g[1][j] = b[0][j] + b[1][j] + b[2][j];
        g[2][j] = b[0][j] - b[1][j] + b[2][j];
        g[3][j] = 2 * b[2][j];
    }
    #pragma unroll
    for (int i = 0; i < 4; i++) {
        int v0 = 2 * g[i][0];
        int v1 = g[i][0] + g[i][1] + g[i][2];
        int v2 = g[i][0] - g[i][1] + g[i][2];
        int v3 = 2 * g[i][2];
        V[(size_t)(i * 4 + 0) * VPLANE + idx] = (char)v0;
        V[(size_t)(i * 4 + 1) * VPLANE + idx] = (char)v1;
        V[(size_t)(i * 4 + 2) * VPLANE + idx] = (char)v2;
        V[(size_t)(i * 4 + 3) * VPLANE + idx] = (char)v3;
    }
}

// -------- wino U: xb NHWC int8 -> U[t][tile*256+c] int8  (B^T d B, |U|<=4)
__global__ void wino_u_kernel(const char* __restrict__ xb, char* __restrict__ U) {
    int item = blockIdx.x * 256 + threadIdx.x;   // tile*64 + cgroup
    int tile = item >> 6;
    int cg = item & 63;                          // 4 channels per thread
    int n = tile / NT2;
    int rt = tile - n * NT2;
    int ty = rt / 14, tx = rt - ty * 14;
    int h0 = 2 * ty - 1, w0 = 2 * tx - 1;
    const char* base = xb + ((size_t)n * HWSZ) * CCH + cg * 4;

    uint32_t d[4][4];
    #pragma unroll
    for (int i = 0; i < 4; i++) {
        int h = h0 + i;
        #pragma unroll
        for (int j = 0; j < 4; j++) {
            int w = w0 + j;
            d[i][j] = (((unsigned)h < 28u) & ((unsigned)w < 28u))
                ? *reinterpret_cast<const uint32_t*>(base + (size_t)(h * HH28 + w) * CCH)
                : 0u;
        }
    }
    uint32_t r[4][4];
    #pragma unroll
    for (int j = 0; j < 4; j++) {
        r[0][j] = __vsub4(d[0][j], d[2][j]);
        r[1][j] = __vadd4(d[1][j], d[2][j]);
        r[2][j] = __vsub4(d[2][j], d[1][j]);
        r[3][j] = __vsub4(d[1][j], d[3][j]);
    }
    #pragma unroll
    for (int i = 0; i < 4; i++) {
        uint32_t u0 = __vsub4(r[i][0], r[i][2]);
        uint32_t u1 = __vadd4(r[i][1], r[i][2]);
        uint32_t u2 = __vsub4(r[i][2], r[i][1]);
        uint32_t u3 = __vsub4(r[i][1], r[i][3]);
        size_t off = (size_t)tile * CCH + cg * 4;
        *reinterpret_cast<uint32_t*>(U + (size_t)(i * 4 + 0) * UPLANE + off) = u0;
        *reinterpret_cast<uint32_t*>(U + (size_t)(i * 4 + 1) * UPLANE + off) = u1;
        *reinterpret_cast<uint32_t*>(U + (size_t)(i * 4 + 2) * UPLANE + off) = u2;
        *reinterpret_cast<uint32_t*>(U + (size_t)(i * 4 + 3) * UPLANE + off) = u3;
    }
}

// -------- wino GEMM: for t in 0..15: Mhat = U[t]*V[t]^T, fold into Y, write col-major
// grid (392, 4): M-tile 32, N-tile 64; warps 2x4, warp tile 16x16
// 3-stage cp.async ring, one __syncthreads per chunk, occupancy 3
template <bool RESID>
__global__ void __launch_bounds__(256, 3)
wino_gemm(const char* __restrict__ U,
          const char* __restrict__ V,
          const float* __restrict__ xres,
          void* __restrict__ outp) {
    __shared__ __align__(16) char sm[3][STAGE];

    int tid = threadIdx.x, wid = tid >> 5, lane = tid & 31;
    int g = lane >> 2, tg = lane & 3;
    int warpM = wid & 1, warpN = wid >> 1;    // 2 x 4 warps, warp tile 16x16

    // cp.async mapping: A = 128 16B units (tid<128: row=tid>>2, u=tid&3)
    //                   B = 256 16B units (row=tid>>2, u=tid&3)
    int lrow = tid >> 2, lu = tid & 3;
    const char* Ubase = U + ((size_t)blockIdx.x * 32 + lrow) * CCH + lu * 16;   // valid for tid<128
    const char* Vbase = V + ((size_t)blockIdx.y * 64 + lrow) * CCH + lu * 16;
    uint32_t dstA = smem_u32(&sm[0][0]) + lrow * AROW + lu * 16;
    uint32_t dstB = smem_u32(&sm[0][0]) + A_HALF + lrow * AROW + lu * 16;
    bool doA = (tid < 128);

    auto issue = [&](int chunk, int s) {
        int t = chunk >> 2, kc = chunk & 3;
        if (doA) cpa16(dstA + s * STAGE, Ubase + (size_t)t * UPLANE + kc * 64);
        cpa16(dstB + s * STAGE, Vbase + (size_t)t * VPLANE + kc * 64);
        asm volatile("cp.async.commit_group;" ::: "memory");
    };

    int Y[2][4][4];
    int acc[2][4];
    #pragma unroll
    for (int ni = 0; ni < 2; ni++)
        #pragma unroll
        for (int j = 0; j < 4; j++) {
            acc[ni][j] = 0;
            #pragma unroll
            for (int p = 0; p < 4; p++) Y[ni][j][p] = 0;
        }

    issue(0, 0);
    issue(1, 1);
    int s = 0, s2 = 2;    // s = stage of current chunk, s2 = stage for chunk+2
    #pragma unroll 1
    for (int chunk = 0; chunk < 64; ++chunk) {
        if (chunk < 63) {
            asm volatile("cp.async.wait_group 1;" ::: "memory");
        } else {
            asm volatile("cp.async.wait_group 0;" ::: "memory");
        }
        __syncthreads();
        if (chunk + 2 < 64) issue(chunk + 2, s2);

        const char* As = sm[s];
        const char* Bs = sm[s] + A_HALF;
        #pragma unroll
        for (int ks = 0; ks < 2; ks++) {
            int ko = ks * 32;
            uint32_t a[4], b[2][2];
            {
                int r = warpM * 16 + g;
                a[0] = *reinterpret_cast<const uint32_t*>(As + r * AROW + ko + tg * 4);
                a[1] = *reinterpret_cast<const uint32_t*>(As + (r + 8) * AROW + ko + tg * 4);
                a[2] = *reinterpret_cast<const uint32_t*>(As + r * AROW + ko + 16 + tg * 4);
                a[3] = *reinterpret_cast<const uint32_t*>(As + (r + 8) * AROW + ko + 16 + tg * 4);
            }
            #pragma unroll
            for (int ni = 0; ni < 2; ni++) {
                int c = warpN * 16 + ni * 8 + g;
                b[ni][0] = *reinterpret_cast<const uint32_t*>(Bs + c * AROW + ko + tg * 4);
                b[ni][1] = *reinterpret_cast<const uint32_t*>(Bs + c * AROW + ko + 16 + tg * 4);
            }
            #pragma unroll
            for (int ni = 0; ni < 2; ni++)
                mma_s8(acc[ni], a, b[ni]);
        }

        if ((chunk & 3) == 3) {
            // fold Mhat (acc) of t = chunk>>2 into Y, reset acc
            int t = chunk >> 2;
            int tr = t >> 2, tc = t & 3;
            int cr0 = (tr <= 2) ? 1 : 0;
            int cr1 = (tr == 0) ? 0 : ((tr == 1) ? 1 : -1);
            int cc0 = (tc <= 2) ? 1 : 0;
            int cc1 = (tc == 0) ? 0 : ((tc == 1) ? 1 : -1);
            #pragma unroll
            for (int ni = 0; ni < 2; ni++)
                #pragma unroll
                for (int j = 0; j < 4; j++) {
                    int v = acc[ni][j];
                    Y[ni][j][0] += cr0 * cc0 * v;
                    Y[ni][j][1] += cr0 * cc1 * v;
                    Y[ni][j][2] += cr1 * cc0 * v;
                    Y[ni][j][3] += cr1 * cc1 * v;
                    acc[ni][j] = 0;
                }
        }
        s = (s == 2) ? 0 : s + 1;
        s2 = (s2 == 2) ? 0 : s2 + 1;
    }

    // epilogue: each Mhat element -> 2x2 output pixels, col-major [c][m]
    #pragma unroll
    for (int j = 0; j < 4; j++) {
        int mp = blockIdx.x * 32 + warpM * 16 + g + 8 * (j >> 1);  // wino row
        int n = mp / NT2;
        int rt = mp - n * NT2;
        int ty = rt / 14, tx = rt - ty * 14;
        int hwbase = (2 * ty) * HH28 + 2 * tx;
        int mbase = n * HWSZ + hwbase;
        #pragma unroll
        for (int ni = 0; ni < 2; ni++) {
            int c = blockIdx.y * 64 + warpN * 16 + ni * 8 + 2 * tg + (j & 1);
            size_t obase = (size_t)c * NHW + mbase;
            size_t rbase = ((size_t)n * CCH + c) * HWSZ + hwbase;
            #pragma unroll
            for (int p = 0; p < 4; p++) {
                size_t off = (p >> 1) * HH28 + (p & 1);
                int val = Y[ni][j][p] >> 2;   // exact /4
                if (RESID) {
                    reinterpret_cast<float*>(outp)[obase + off] = (float)val + xres[rbase + off];
                } else {
                    reinterpret_cast<short*>(outp)[obase + off] = (short)val;
                }
            }
        }
    }
}

// -------- stats partials: grid (256, NSLICE), block 256
template <typename T>
__global__ void stats_part(const T* __restrict__ ycm,
                           float* __restrict__ ps, float* __restrict__ pq) {
    int c = blockIdx.x, sl = blockIdx.y;
    const T* p = ycm + (size_t)c * NHW + sl * SLICELEN;
    float s = 0.f, q = 0.f;
    for (int i = threadIdx.x; i < SLICELEN; i += 256) {
        float v = (float)p[i];
        s += v; q += v * v;
    }
    __shared__ float rs[256], rq[256];
    rs[threadIdx.x] = s; rq[threadIdx.x] = q;
    __syncthreads();
    for (int o = 128; o > 0; o >>= 1) {
        if (threadIdx.x < o) { rs[threadIdx.x] += rs[threadIdx.x + o]; rq[threadIdx.x] += rq[threadIdx.x + o]; }
        __syncthreads();
    }
    if (threadIdx.x == 0) { ps[c * NSLICE + sl] = rs[0]; pq[c * NSLICE + sl] = rq[0]; }
}

// -------- stats finalize: 1 block, 256 threads (one channel each)
__global__ void stats_fin(const float* __restrict__ ps, const float* __restrict__ pq,
                          const float* __restrict__ gamma, const float* __restrict__ beta,
                          float* __restrict__ scl, float* __restrict__ bia) {
    int c = threadIdx.x;
    float s = 0.f, q = 0.f;
    #pragma unroll
    for (int j = 0; j < NSLICE; j++) { s += ps[c * NSLICE + j]; q += pq[c * NSLICE + j]; }
    float mean = s / (float)NHW;
    float var  = q / (float)NHW - mean * mean;
    float inv  = rsqrtf(var + 1e-5f);
    float sc   = gamma[c] * inv;
    scl[c] = sc;
    bia[c] = beta[c] - mean * sc;
}

// -------- binarize BN1 output: [c][m] int16 -> [m][c] int8 +-1
__global__ void binarize_kernel(const short* __restrict__ ycm,
                                const float* __restrict__ scl, const float* __restrict__ bia,
                                char* __restrict__ xb2) {
    __shared__ short t[32][33];
    __shared__ float sc[32], bi[32];
    int tx = threadIdx.x, ty = threadIdx.y;
    int c0 = blockIdx.y * 32, m0 = blockIdx.x * 32;
    if (ty == 0) { sc[tx] = scl[c0 + tx]; bi[tx] = bia[c0 + tx]; }
    #pragma unroll
    for (int j = 0; j < 4; j++) {
        int c = c0 + ty + j * 8;
        t[ty + j * 8][tx] = ycm[(size_t)c * NHW + m0 + tx];
    }
    __syncthreads();
    #pragma unroll
    for (int j = 0; j < 4; j++) {
        int m = m0 + ty + j * 8;
        float v = (float)t[tx][ty + j * 8] * sc[tx] + bi[tx];
        xb2[(size_t)m * CCH + c0 + tx] = (v >= 0.f) ? 1 : -1;
    }
}

// -------- final: BN2 + hardtanh + NCHW
__global__ void final_kernel(const float* __restrict__ y2,
                             const float* __restrict__ scl, const float* __restrict__ bia,
                             float* __restrict__ out) {
    size_t total = (size_t)CCH * NHW;
    for (size_t idx = (size_t)blockIdx.x * blockDim.x + threadIdx.x; idx < total;
         idx += (size_t)gridDim.x * blockDim.x) {
        unsigned c = (unsigned)(idx / NHW);
        unsigned r = (unsigned)(idx - (size_t)c * NHW);
        unsigned n = r / HWSZ;
        unsigned hw = r - n * HWSZ;
        float v = y2[idx] * scl[c] + bia[c];
        v = fminf(fmaxf(v, -1.f), 1.f);
        out[((size_t)n * CCH + c) * HWSZ + hw] = v;
    }
}

// ---------------------------------------------------------------- launcher
extern "C" void kernel_launch(void* const* d_in, const int* in_sizes, int n_in,
                              void* d_out, int out_size) {
    const float* x   = (const float*)d_in[0];
    const float* w1  = (const float*)d_in[1];
    const float* w2  = (const float*)d_in[2];
    const float* ga1 = (const float*)d_in[3];
    const float* be1 = (const float*)d_in[4];
    const float* ga2 = (const float*)d_in[5];
    const float* be2 = (const float*)d_in[6];
    float* out = (float*)d_out;

    char *xb1, *xb2, *U, *V1, *V2;
    float *y2, *ps, *pq, *s1, *bi1, *s2, *bi2;
    short* y1;
    cudaGetSymbolAddress((void**)&xb1, g_xb1);
    cudaGetSymbolAddress((void**)&xb2, g_xb2);
    cudaGetSymbolAddress((void**)&U,   g_U);
    cudaGetSymbolAddress((void**)&V1,  g_V1);
    cudaGetSymbolAddress((void**)&V2,  g_V2);
    cudaGetSymbolAddress((void**)&y1,  g_y1);
    cudaGetSymbolAddress((void**)&y2,  g_y2);
    cudaGetSymbolAddress((void**)&ps,  g_ps);
    cudaGetSymbolAddress((void**)&pq,  g_pq);
    cudaGetSymbolAddress((void**)&s1,  g_s1);
    cudaGetSymbolAddress((void**)&bi1, g_bi1);
    cudaGetSymbolAddress((void**)&s2,  g_s2);
    cudaGetSymbolAddress((void**)&bi2, g_bi2);

    prep_x_kernel<<<dim3(25, 8, 64), dim3(32, 8)>>>(x, xb1);
    wino_v_kernel<<<256, 256>>>(w1, V1);
    wino_v_kernel<<<256, 256>>>(w2, V2);

    wino_u_kernel<<<MWIN * 64 / 256, 256>>>(xb1, U);
    wino_gemm<false><<<dim3(392, 4), 256>>>(U, V1, nullptr, (void*)y1);
    stats_part<short><<<dim3(256, NSLICE), 256>>>(y1, ps, pq);
    stats_fin<<<1, 256>>>(ps, pq, ga1, be1, s1, bi1);
    binarize_kernel<<<dim3(1568, 8), dim3(32, 8)>>>(y1, s1, bi1, xb2);

    wino_u_kernel<<<MWIN * 64 / 256, 256>>>(xb2, U);
    wino_gemm<true><<<dim3(392, 4), 256>>>(U, V2, x, (void*)y2);
    stats_part<float><<<dim3(256, NSLICE), 256>>>(y2, ps, pq);
    stats_fin<<<1, 256>>>(ps, pq, ga2, be2, s2, bi2);
    final_kernel<<<1184, 256>>>(y2, s2, bi2, out);
}

// round 15
// speedup vs baseline: 1.7757x; 1.0250x over previous
#include <cuda_runtime.h>
#include <cstdint>

#define NIMG 64
#define CCH  256
#define HH28 28
#define HWSZ 784
#define NHW  50176
#define NT2  196          // winograd tiles per image (14x14)
#define MWIN 12544        // 64*196 tile-rows
#define UPLANE (MWIN * CCH)   // bytes per U[t] plane (int8)
#define VPLANE (CCH * CCH)
#define NSLICE 8
#define SLICELEN (NHW / NSLICE)

// wino gemm smem: 3 stages, each A(32 x 80B) + B(64 x 80B)
#define AROW 80
#define A_HALF (32 * AROW)
#define B_HALF (64 * AROW)
#define STAGE (A_HALF + B_HALF)

// ---------------------------------------------------------------- helpers
__device__ __forceinline__ uint32_t smem_u32(const void* p) {
    uint32_t a;
    asm("{ .reg .u64 t; cvta.to.shared.u64 t, %1; cvt.u32.u64 %0, t; }" : "=r"(a) : "l"(p));
    return a;
}
__device__ __forceinline__ void cpa16(uint32_t dst, const void* src) {
    asm volatile("cp.async.cg.shared.global [%0], [%1], 16;"
                 :: "r"(dst), "l"(src) : "memory");
}
__device__ __forceinline__ void mma_s8(int* d, const uint32_t* a, const uint32_t* b) {
    asm volatile(
        "mma.sync.aligned.m16n8k32.row.col.s32.s8.s8.s32 "
        "{%0,%1,%2,%3}, {%4,%5,%6,%7}, {%8,%9}, {%0,%1,%2,%3};"
        : "+r"(d[0]), "+r"(d[1]), "+r"(d[2]), "+r"(d[3])
        : "r"(a[0]), "r"(a[1]), "r"(a[2]), "r"(a[3]), "r"(b[0]), "r"(b[1]));
}

// ---------------------------------------------------------------- scratch
__device__ __align__(256) char  g_xb1[(size_t)NHW * CCH];   // binarized x, NHWC int8
__device__ __align__(256) char  g_xb2[(size_t)NHW * CCH];   // binarized BN1 out, NHWC int8
__device__ __align__(256) char  g_U[(size_t)16 * UPLANE];   // winograd input transform
__device__ __align__(256) char  g_V1[16 * VPLANE];          // winograd weight transform
__device__ __align__(256) char  g_V2[16 * VPLANE];
__device__ short g_y1[(size_t)CCH * NHW];                   // conv1 out, col-major
__device__ float g_y2[(size_t)CCH * NHW];                   // conv2+resid, col-major
__device__ float g_ps[CCH * NSLICE], g_pq[CCH * NSLICE];    // stats partials
__device__ float g_s1[CCH], g_bi1[CCH], g_s2[CCH], g_bi2[CCH];

// -------- K1: binarize x -> NHWC int8 (transpose NCHW -> NHWC)
__global__ void prep_x_kernel(const float* __restrict__ x,
                              char* __restrict__ xb1) {
    __shared__ float t[32][33];
    int tx = threadIdx.x, ty = threadIdx.y;
    int n  = blockIdx.z;
    int c0 = blockIdx.y * 32;
    int p0 = blockIdx.x * 32;
    #pragma unroll
    for (int j = 0; j < 4; j++) {
        int c = c0 + ty + j * 8;
        int p = p0 + tx;
        float v = 0.f;
        if (p < HWSZ) v = x[((size_t)n * CCH + c) * HWSZ + p];
        t[ty + j * 8][tx] = v;
    }
    __syncthreads();
    #pragma unroll
    for (int j = 0; j < 4; j++) {
        int p = p0 + ty + j * 8;
        if (p < HWSZ) {
            float v = t[tx][ty + j * 8];
            xb1[((size_t)(n * HWSZ + p)) * CCH + c0 + tx] = (v >= 0.f) ? 1 : -1;
        }
    }
}

// -------- wino V: w (OIHW f32) -> V[t][cout*256+cin] int8, V = (2G) sign(w) (2G)^T
__global__ void wino_v_kernel(const float* __restrict__ w, char* __restrict__ V) {
    int idx = blockIdx.x * 256 + threadIdx.x;   // cout*256 + cin
    const float* p = w + (size_t)idx * 9;
    int b[3][3];
    #pragma unroll
    for (int i = 0; i < 3; i++)
        #pragma unroll
        for (int j = 0; j < 3; j++)
            b[i][j] = (p[i * 3 + j] >= 0.f) ? 1 : -1;
    int g[4][3];
    #pragma unroll
    for (int j = 0; j < 3; j++) {
        g[0][j] = 2 * b[0][j];
        g[1][j] = b[0][j] + b[1][j] + b[2][j];
        g[2][j] = b[0][j] - b[1][j] + b[2][j];
        g[3][j] = 2 * b[2][j];
    }
    #pragma unroll
    for (int i = 0; i < 4; i++) {
        int v0 = 2 * g[i][0];
        int v1 = g[i][0] + g[i][1] + g[i][2];
        int v2 = g[i][0] - g[i][1] + g[i][2];
        int v3 = 2 * g[i][2];
        V[(size_t)(i * 4 + 0) * VPLANE + idx] = (char)v0;
        V[(size_t)(i * 4 + 1) * VPLANE + idx] = (char)v1;
        V[(size_t)(i * 4 + 2) * VPLANE + idx] = (char)v2;
        V[(size_t)(i * 4 + 3) * VPLANE + idx] = (char)v3;
    }
}

// -------- wino U: xb NHWC int8 -> U[t][tile*256+c] int8  (B^T d B, |U|<=4)
__global__ void wino_u_kernel(const char* __restrict__ xb, char* __restrict__ U) {
    int item = blockIdx.x * 256 + threadIdx.x;   // tile*64 + cgroup
    int tile = item >> 6;
    int cg = item & 63;                          // 4 channels per thread
    int n = tile / NT2;
    int rt = tile - n * NT2;
    int ty = rt / 14, tx = rt - ty * 14;
    int h0 = 2 * ty - 1, w0 = 2 * tx - 1;
    const char* base = xb + ((size_t)n * HWSZ) * CCH + cg * 4;

    uint32_t d[4][4];
    #pragma unroll
    for (int i = 0; i < 4; i++) {
        int h = h0 + i;
        #pragma unroll
        for (int j = 0; j < 4; j++) {
            int w = w0 + j;
            d[i][j] = (((unsigned)h < 28u) & ((unsigned)w < 28u))
                ? *reinterpret_cast<const uint32_t*>(base + (size_t)(h * HH28 + w) * CCH)
                : 0u;
        }
    }
    uint32_t r[4][4];
    #pragma unroll
    for (int j = 0; j < 4; j++) {
        r[0][j] = __vsub4(d[0][j], d[2][j]);
        r[1][j] = __vadd4(d[1][j], d[2][j]);
        r[2][j] = __vsub4(d[2][j], d[1][j]);
        r[3][j] = __vsub4(d[1][j], d[3][j]);
    }
    #pragma unroll
    for (int i = 0; i < 4; i++) {
        uint32_t u0 = __vsub4(r[i][0], r[i][2]);
        uint32_t u1 = __vadd4(r[i][1], r[i][2]);
        uint32_t u2 = __vsub4(r[i][2], r[i][1]);
        uint32_t u3 = __vsub4(r[i][1], r[i][3]);
        size_t off = (size_t)tile * CCH + cg * 4;
        *reinterpret_cast<uint32_t*>(U + (size_t)(i * 4 + 0) * UPLANE + off) = u0;
        *reinterpret_cast<uint32_t*>(U + (size_t)(i * 4 + 1) * UPLANE + off) = u1;
        *reinterpret_cast<uint32_t*>(U + (size_t)(i * 4 + 2) * UPLANE + off) = u2;
        *reinterpret_cast<uint32_t*>(U + (size_t)(i * 4 + 3) * UPLANE + off) = u3;
    }
}

// -------- wino GEMM: for t in 0..15: Mhat = U[t]*V[t]^T, fold into Y, write col-major
// grid (392, 4): M-tile 32, N-tile 64; warps 2x4, warp tile 16x16
// 3-stage cp.async ring, one __syncthreads per chunk, occupancy 3
template <bool RESID>
__global__ void __launch_bounds__(256, 3)
wino_gemm(const char* __restrict__ U,
          const char* __restrict__ V,
          const float* __restrict__ xres,
          void* __restrict__ outp) {
    __shared__ __align__(16) char sm[3][STAGE];

    int tid = threadIdx.x, wid = tid >> 5, lane = tid & 31;
    int g = lane >> 2, tg = lane & 3;
    int warpM = wid & 1, warpN = wid >> 1;    // 2 x 4 warps, warp tile 16x16

    int lrow = tid >> 2, lu = tid & 3;
    const char* Ubase = U + ((size_t)blockIdx.x * 32 + lrow) * CCH + lu * 16;   // valid for tid<128
    const char* Vbase = V + ((size_t)blockIdx.y * 64 + lrow) * CCH + lu * 16;
    uint32_t dstA = smem_u32(&sm[0][0]) + lrow * AROW + lu * 16;
    uint32_t dstB = smem_u32(&sm[0][0]) + A_HALF + lrow * AROW + lu * 16;
    bool doA = (tid < 128);

    auto issue = [&](int chunk, int s) {
        int t = chunk >> 2, kc = chunk & 3;
        if (doA) cpa16(dstA + s * STAGE, Ubase + (size_t)t * UPLANE + kc * 64);
        cpa16(dstB + s * STAGE, Vbase + (size_t)t * VPLANE + kc * 64);
        asm volatile("cp.async.commit_group;" ::: "memory");
    };

    int Y[2][4][4];
    int acc[2][4];
    #pragma unroll
    for (int ni = 0; ni < 2; ni++)
        #pragma unroll
        for (int j = 0; j < 4; j++) {
            acc[ni][j] = 0;
            #pragma unroll
            for (int p = 0; p < 4; p++) Y[ni][j][p] = 0;
        }

    issue(0, 0);
    issue(1, 1);
    int s = 0, s2 = 2;
    #pragma unroll 1
    for (int chunk = 0; chunk < 64; ++chunk) {
        if (chunk < 63) {
            asm volatile("cp.async.wait_group 1;" ::: "memory");
        } else {
            asm volatile("cp.async.wait_group 0;" ::: "memory");
        }
        __syncthreads();
        if (chunk + 2 < 64) issue(chunk + 2, s2);

        const char* As = sm[s];
        const char* Bs = sm[s] + A_HALF;
        #pragma unroll
        for (int ks = 0; ks < 2; ks++) {
            int ko = ks * 32;
            uint32_t a[4], b[2][2];
            {
                int r = warpM * 16 + g;
                a[0] = *reinterpret_cast<const uint32_t*>(As + r * AROW + ko + tg * 4);
                a[1] = *reinterpret_cast<const uint32_t*>(As + (r + 8) * AROW + ko + tg * 4);
                a[2] = *reinterpret_cast<const uint32_t*>(As + r * AROW + ko + 16 + tg * 4);
                a[3] = *reinterpret_cast<const uint32_t*>(As + (r + 8) * AROW + ko + 16 + tg * 4);
            }
            #pragma unroll
            for (int ni = 0; ni < 2; ni++) {
                int c = warpN * 16 + ni * 8 + g;
                b[ni][0] = *reinterpret_cast<const uint32_t*>(Bs + c * AROW + ko + tg * 4);
                b[ni][1] = *reinterpret_cast<const uint32_t*>(Bs + c * AROW + ko + 16 + tg * 4);
            }
            #pragma unroll
            for (int ni = 0; ni < 2; ni++)
                mma_s8(acc[ni], a, b[ni]);
        }

        if ((chunk & 3) == 3) {
            int t = chunk >> 2;
            int tr = t >> 2, tc = t & 3;
            int cr0 = (tr <= 2) ? 1 : 0;
            int cr1 = (tr == 0) ? 0 : ((tr == 1) ? 1 : -1);
            int cc0 = (tc <= 2) ? 1 : 0;
            int cc1 = (tc == 0) ? 0 : ((tc == 1) ? 1 : -1);
            #pragma unroll
            for (int ni = 0; ni < 2; ni++)
                #pragma unroll
                for (int j = 0; j < 4; j++) {
                    int v = acc[ni][j];
                    Y[ni][j][0] += cr0 * cc0 * v;
                    Y[ni][j][1] += cr0 * cc1 * v;
                    Y[ni][j][2] += cr1 * cc0 * v;
                    Y[ni][j][3] += cr1 * cc1 * v;
                    acc[ni][j] = 0;
                }
        }
        s = (s == 2) ? 0 : s + 1;
        s2 = (s2 == 2) ? 0 : s2 + 1;
    }

    // epilogue: each Mhat element -> 2x2 output pixels, col-major [c][m]
    #pragma unroll
    for (int j = 0; j < 4; j++) {
        int mp = blockIdx.x * 32 + warpM * 16 + g + 8 * (j >> 1);  // wino row
        int n = mp / NT2;
        int rt = mp - n * NT2;
        int ty = rt / 14, tx = rt - ty * 14;
        int hwbase = (2 * ty) * HH28 + 2 * tx;
        int mbase = n * HWSZ + hwbase;
        #pragma unroll
        for (int ni = 0; ni < 2; ni++) {
            int c = blockIdx.y * 64 + warpN * 16 + ni * 8 + 2 * tg + (j & 1);
            size_t obase = (size_t)c * NHW + mbase;
            size_t rbase = ((size_t)n * CCH + c) * HWSZ + hwbase;
            #pragma unroll
            for (int p = 0; p < 4; p++) {
                size_t off = (p >> 1) * HH28 + (p & 1);
                int val = Y[ni][j][p] >> 2;   // exact /4
                if (RESID) {
                    reinterpret_cast<float*>(outp)[obase + off] = (float)val + xres[rbase + off];
                } else {
                    reinterpret_cast<short*>(outp)[obase + off] = (short)val;
                }
            }
        }
    }
}

// -------- stats partials (float, vectorized float4): grid (256, NSLICE)
__global__ void stats_part_f4(const float* __restrict__ ycm,
                              float* __restrict__ ps, float* __restrict__ pq) {
    int c = blockIdx.x, sl = blockIdx.y;
    const float4* p = reinterpret_cast<const float4*>(ycm + (size_t)c * NHW + sl * SLICELEN);
    float s = 0.f, q = 0.f;
    for (int i = threadIdx.x; i < SLICELEN / 4; i += 256) {
        float4 v = p[i];
        s += v.x + v.y + v.z + v.w;
        q += v.x * v.x + v.y * v.y + v.z * v.z + v.w * v.w;
    }
    __shared__ float rs[256], rq[256];
    rs[threadIdx.x] = s; rq[threadIdx.x] = q;
    __syncthreads();
    for (int o = 128; o > 0; o >>= 1) {
        if (threadIdx.x < o) { rs[threadIdx.x] += rs[threadIdx.x + o]; rq[threadIdx.x] += rq[threadIdx.x + o]; }
        __syncthreads();
    }
    if (threadIdx.x == 0) { ps[c * NSLICE + sl] = rs[0]; pq[c * NSLICE + sl] = rq[0]; }
}

// -------- stats partials (short, vectorized short4): grid (256, NSLICE)
__global__ void stats_part_s4(const short* __restrict__ ycm,
                              float* __restrict__ ps, float* __restrict__ pq) {
    int c = blockIdx.x, sl = blockIdx.y;
    const short4* p = reinterpret_cast<const short4*>(ycm + (size_t)c * NHW + sl * SLICELEN);
    float s = 0.f, q = 0.f;
    for (int i = threadIdx.x; i < SLICELEN / 4; i += 256) {
        short4 v = p[i];
        float a = (float)v.x, b = (float)v.y, cc = (float)v.z, d = (float)v.w;
        s += a + b + cc + d;
        q += a * a + b * b + cc * cc + d * d;
    }
    __shared__ float rs[256], rq[256];
    rs[threadIdx.x] = s; rq[threadIdx.x] = q;
    __syncthreads();
    for (int o = 128; o > 0; o >>= 1) {
        if (threadIdx.x < o) { rs[threadIdx.x] += rs[threadIdx.x + o]; rq[threadIdx.x] += rq[threadIdx.x + o]; }
        __syncthreads();
    }
    if (threadIdx.x == 0) { ps[c * NSLICE + sl] = rs[0]; pq[c * NSLICE + sl] = rq[0]; }
}

// -------- stats finalize: 1 block, 256 threads (one channel each)
__global__ void stats_fin(const float* __restrict__ ps, const float* __restrict__ pq,
                          const float* __restrict__ gamma, const float* __restrict__ beta,
                          float* __restrict__ scl, float* __restrict__ bia) {
    int c = threadIdx.x;
    float s = 0.f, q = 0.f;
    #pragma unroll
    for (int j = 0; j < NSLICE; j++) { s += ps[c * NSLICE + j]; q += pq[c * NSLICE + j]; }
    float mean = s / (float)NHW;
    float var  = q / (float)NHW - mean * mean;
    float inv  = rsqrtf(var + 1e-5f);
    float sc   = gamma[c] * inv;
    scl[c] = sc;
    bia[c] = beta[c] - mean * sc;
}

// -------- binarize BN1 output: [c][m] int16 -> [m][c] int8 +-1
__global__ void binarize_kernel(const short* __restrict__ ycm,
                                const float* __restrict__ scl, const float* __restrict__ bia,
                                char* __restrict__ xb2) {
    __shared__ short t[32][33];
    __shared__ float sc[32], bi[32];
    int tx = threadIdx.x, ty = threadIdx.y;
    int c0 = blockIdx.y * 32, m0 = blockIdx.x * 32;
    if (ty == 0) { sc[tx] = scl[c0 + tx]; bi[tx] = bia[c0 + tx]; }
    #pragma unroll
    for (int j = 0; j < 4; j++) {
        int c = c0 + ty + j * 8;
        t[ty + j * 8][tx] = ycm[(size_t)c * NHW + m0 + tx];
    }
    __syncthreads();
    #pragma unroll
    for (int j = 0; j < 4; j++) {
        int m = m0 + ty + j * 8;
        float v = (float)t[tx][ty + j * 8] * sc[tx] + bi[tx];
        xb2[(size_t)m * CCH + c0 + tx] = (v >= 0.f) ? 1 : -1;
    }
}

// -------- final: BN2 + hardtanh + NCHW, float4 vectorized
// grid (NHW/4/256, 256): y = channel, x covers NHW/4 vec elements
__global__ void final_kernel(const float* __restrict__ y2,
                             const float* __restrict__ scl, const float* __restrict__ bia,
                             float* __restrict__ out) {
    int c = blockIdx.y;
    int m4 = blockIdx.x * 256 + threadIdx.x;      // vec index, 0..12543
    float sc = scl[c], bi = bia[c];
    int n = m4 / (HWSZ / 4);
    int hw = (m4 - n * (HWSZ / 4)) * 4;
    float4 v = *reinterpret_cast<const float4*>(y2 + (size_t)c * NHW + m4 * 4);
    v.x = fminf(fmaxf(v.x * sc + bi, -1.f), 1.f);
    v.y = fminf(fmaxf(v.y * sc + bi, -1.f), 1.f);
    v.z = fminf(fmaxf(v.z * sc + bi, -1.f), 1.f);
    v.w = fminf(fmaxf(v.w * sc + bi, -1.f), 1.f);
    *reinterpret_cast<float4*>(out + ((size_t)n * CCH + c) * HWSZ + hw) = v;
}

// ---------------------------------------------------------------- launcher
extern "C" void kernel_launch(void* const* d_in, const int* in_sizes, int n_in,
                              void* d_out, int out_size) {
    const float* x   = (const float*)d_in[0];
    const float* w1  = (const float*)d_in[1];
    const float* w2  = (const float*)d_in[2];
    const float* ga1 = (const float*)d_in[3];
    const float* be1 = (const float*)d_in[4];
    const float* ga2 = (const float*)d_in[5];
    const float* be2 = (const float*)d_in[6];
    float* out = (float*)d_out;

    char *xb1, *xb2, *U, *V1, *V2;
    float *y2, *ps, *pq, *s1, *bi1, *s2, *bi2;
    short* y1;
    cudaGetSymbolAddress((void**)&xb1, g_xb1);
    cudaGetSymbolAddress((void**)&xb2, g_xb2);
    cudaGetSymbolAddress((void**)&U,   g_U);
    cudaGetSymbolAddress((void**)&V1,  g_V1);
    cudaGetSymbolAddress((void**)&V2,  g_V2);
    cudaGetSymbolAddress((void**)&y1,  g_y1);
    cudaGetSymbolAddress((void**)&y2,  g_y2);
    cudaGetSymbolAddress((void**)&ps,  g_ps);
    cudaGetSymbolAddress((void**)&pq,  g_pq);
    cudaGetSymbolAddress((void**)&s1,  g_s1);
    cudaGetSymbolAddress((void**)&bi1, g_bi1);
    cudaGetSymbolAddress((void**)&s2,  g_s2);
    cudaGetSymbolAddress((void**)&bi2, g_bi2);

    prep_x_kernel<<<dim3(25, 8, 64), dim3(32, 8)>>>(x, xb1);
    wino_v_kernel<<<256, 256>>>(w1, V1);
    wino_v_kernel<<<256, 256>>>(w2, V2);

    wino_u_kernel<<<MWIN * 64 / 256, 256>>>(xb1, U);
    wino_gemm<false><<<dim3(392, 4), 256>>>(U, V1, nullptr, (void*)y1);
    stats_part_s4<<<dim3(256, NSLICE), 256>>>(y1, ps, pq);
    stats_fin<<<1, 256>>>(ps, pq, ga1, be1, s1, bi1);
    binarize_kernel<<<dim3(1568, 8), dim3(32, 8)>>>(y1, s1, bi1, xb2);

    wino_u_kernel<<<MWIN * 64 / 256, 256>>>(xb2, U);
    wino_gemm<true><<<dim3(392, 4), 256>>>(U, V2, x, (void*)y2);
    stats_part_f4<<<dim3(256, NSLICE), 256>>>(y2, ps, pq);
    stats_fin<<<1, 256>>>(ps, pq, ga2, be2, s2, bi2);
    final_kernel<<<dim3(NHW / 4 / 256, 256), 256>>>(y2, s2, bi2, out);
}

// round 16
// speedup vs baseline: 1.8258x; 1.0282x over previous
#include <cuda_runtime.h>
#include <cstdint>

#define NIMG 64
#define CCH  256
#define HH28 28
#define HWSZ 784
#define NHW  50176
#define NT2  196          // winograd tiles per image (14x14)
#define MWIN 12544        // 64*196 tile-rows
#define UPLANE (MWIN * CCH)   // bytes per U[t] plane (int8)
#define VPLANE (CCH * CCH)
#define NSLICE 8
#define SLICELEN (NHW / NSLICE)

// wino gemm smem: 3 stages, each A(32 x 80B) + B(64 x 80B)
#define AROW 80
#define A_HALF (32 * AROW)
#define B_HALF (64 * AROW)
#define STAGE (A_HALF + B_HALF)

// ---------------------------------------------------------------- helpers
__device__ __forceinline__ uint32_t smem_u32(const void* p) {
    uint32_t a;
    asm("{ .reg .u64 t; cvta.to.shared.u64 t, %1; cvt.u32.u64 %0, t; }" : "=r"(a) : "l"(p));
    return a;
}
__device__ __forceinline__ void cpa16(uint32_t dst, const void* src) {
    asm volatile("cp.async.cg.shared.global [%0], [%1], 16;"
                 :: "r"(dst), "l"(src) : "memory");
}
__device__ __forceinline__ void mma_s8(int* d, const uint32_t* a, const uint32_t* b) {
    asm volatile(
        "mma.sync.aligned.m16n8k32.row.col.s32.s8.s8.s32 "
        "{%0,%1,%2,%3}, {%4,%5,%6,%7}, {%8,%9}, {%0,%1,%2,%3};"
        : "+r"(d[0]), "+r"(d[1]), "+r"(d[2]), "+r"(d[3])
        : "r"(a[0]), "r"(a[1]), "r"(a[2]), "r"(a[3]), "r"(b[0]), "r"(b[1]));
}
__device__ __forceinline__ void ldsm_x4(uint32_t* r, uint32_t addr) {
    asm volatile("ldmatrix.sync.aligned.m8n8.x4.shared.b16 {%0,%1,%2,%3}, [%4];"
                 : "=r"(r[0]), "=r"(r[1]), "=r"(r[2]), "=r"(r[3]) : "r"(addr));
}

// ---------------------------------------------------------------- scratch
__device__ __align__(256) char  g_xb1[(size_t)NHW * CCH];   // binarized x, NHWC int8
__device__ __align__(256) char  g_xb2[(size_t)NHW * CCH];   // binarized BN1 out, NHWC int8
__device__ __align__(256) char  g_U[(size_t)16 * UPLANE];   // winograd input transform
__device__ __align__(256) char  g_V1[16 * VPLANE];          // winograd weight transform
__device__ __align__(256) char  g_V2[16 * VPLANE];
__device__ short g_y1[(size_t)CCH * NHW];                   // conv1 out, col-major
__device__ float g_y2[(size_t)CCH * NHW];                   // conv2+resid, col-major
__device__ float g_ps[CCH * NSLICE], g_pq[CCH * NSLICE];    // stats partials
__device__ float g_s1[CCH], g_bi1[CCH], g_s2[CCH], g_bi2[CCH];

// -------- K1: binarize x -> NHWC int8 (transpose NCHW -> NHWC)
__global__ void prep_x_kernel(const float* __restrict__ x,
                              char* __restrict__ xb1) {
    __shared__ float t[32][33];
    int tx = threadIdx.x, ty = threadIdx.y;
    int n  = blockIdx.z;
    int c0 = blockIdx.y * 32;
    int p0 = blockIdx.x * 32;
    #pragma unroll
    for (int j = 0; j < 4; j++) {
        int c = c0 + ty + j * 8;
        int p = p0 + tx;
        float v = 0.f;
        if (p < HWSZ) v = x[((size_t)n * CCH + c) * HWSZ + p];
        t[ty + j * 8][tx] = v;
    }
    __syncthreads();
    #pragma unroll
    for (int j = 0; j < 4; j++) {
        int p = p0 + ty + j * 8;
        if (p < HWSZ) {
            float v = t[tx][ty + j * 8];
            xb1[((size_t)(n * HWSZ + p)) * CCH + c0 + tx] = (v >= 0.f) ? 1 : -1;
        }
    }
}

// -------- wino V: w (OIHW f32) -> V[t][cout*256+cin] int8, V = (2G) sign(w) (2G)^T
__global__ void wino_v_kernel(const float* __restrict__ w, char* __restrict__ V) {
    int idx = blockIdx.x * 256 + threadIdx.x;   // cout*256 + cin
    const float* p = w + (size_t)idx * 9;
    int b[3][3];
    #pragma unroll
    for (int i = 0; i < 3; i++)
        #pragma unroll
        for (int j = 0; j < 3; j++)
            b[i][j] = (p[i * 3 + j] >= 0.f) ? 1 : -1;
    int g[4][3];
    #pragma unroll
    for (int j = 0; j < 3; j++) {
        g[0][j] = 2 * b[0][j];
        g[1][j] = b[0][j] + b[1][j] + b[2][j];
        g[2][j] = b[0][j] - b[1][j] + b[2][j];
        g[3][j] = 2 * b[2][j];
    }
    #pragma unroll
    for (int i = 0; i < 4; i++) {
        int v0 = 2 * g[i][0];
        int v1 = g[i][0] + g[i][1] + g[i][2];
        int v2 = g[i][0] - g[i][1] + g[i][2];
        int v3 = 2 * g[i][2];
        V[(size_t)(i * 4 + 0) * VPLANE + idx] = (char)v0;
        V[(size_t)(i * 4 + 1) * VPLANE + idx] = (char)v1;
        V[(size_t)(i * 4 + 2) * VPLANE + idx] = (char)v2;
        V[(size_t)(i * 4 + 3) * VPLANE + idx] = (char)v3;
    }
}

// -------- wino U: xb NHWC int8 -> U[t][tile*256+c] int8  (B^T d B, |U|<=4)
__global__ void wino_u_kernel(const char* __restrict__ xb, char* __restrict__ U) {
    int item = blockIdx.x * 256 + threadIdx.x;   // tile*64 + cgroup
    int tile = item >> 6;
    int cg = item & 63;                          // 4 channels per thread
    int n = tile / NT2;
    int rt = tile - n * NT2;
    int ty = rt / 14, tx = rt - ty * 14;
    int h0 = 2 * ty - 1, w0 = 2 * tx - 1;
    const char* base = xb + ((size_t)n * HWSZ) * CCH + cg * 4;

    uint32_t d[4][4];
    #pragma unroll
    for (int i = 0; i < 4; i++) {
        int h = h0 + i;
        #pragma unroll
        for (int j = 0; j < 4; j++) {
            int w = w0 + j;
            d[i][j] = (((unsigned)h < 28u) & ((unsigned)w < 28u))
                ? *reinterpret_cast<const uint32_t*>(base + (size_t)(h * HH28 + w) * CCH)
                : 0u;
        }
    }
    uint32_t r[4][4];
    #pragma unroll
    for (int j = 0; j < 4; j++) {
        r[0][j] = __vsub4(d[0][j], d[2][j]);
        r[1][j] = __vadd4(d[1][j], d[2][j]);
        r[2][j] = __vsub4(d[2][j], d[1][j]);
        r[3][j] = __vsub4(d[1][j], d[3][j]);
    }
    #pragma unroll
    for (int i = 0; i < 4; i++) {
        uint32_t u0 = __vsub4(r[i][0], r[i][2]);
        uint32_t u1 = __vadd4(r[i][1], r[i][2]);
        uint32_t u2 = __vsub4(r[i][2], r[i][1]);
        uint32_t u3 = __vsub4(r[i][1], r[i][3]);
        size_t off = (size_t)tile * CCH + cg * 4;
        *reinterpret_cast<uint32_t*>(U + (size_t)(i * 4 + 0) * UPLANE + off) = u0;
        *reinterpret_cast<uint32_t*>(U + (size_t)(i * 4 + 1) * UPLANE + off) = u1;
        *reinterpret_cast<uint32_t*>(U + (size_t)(i * 4 + 2) * UPLANE + off) = u2;
        *reinterpret_cast<uint32_t*>(U + (size_t)(i * 4 + 3) * UPLANE + off) = u3;
    }
}

// -------- wino GEMM: for t in 0..15: Mhat = U[t]*V[t]^T, fold into Y, write col-major
// grid (392, 4): M-tile 32, N-tile 64; warps 2x4, warp tile 16x16
// 3-stage cp.async ring, ldmatrix fragment loads, occupancy 3
template <bool RESID>
__global__ void __launch_bounds__(256, 3)
wino_gemm(const char* __restrict__ U,
          const char* __restrict__ V,
          const float* __restrict__ xres,
          void* __restrict__ outp) {
    __shared__ __align__(16) char sm[3][STAGE];

    int tid = threadIdx.x, wid = tid >> 5, lane = tid & 31;
    int g = lane >> 2, tg = lane & 3;
    int warpM = wid & 1, warpN = wid >> 1;    // 2 x 4 warps, warp tile 16x16

    int lrow = tid >> 2, lu = tid & 3;
    const char* Ubase = U + ((size_t)blockIdx.x * 32 + lrow) * CCH + lu * 16;   // valid for tid<128
    const char* Vbase = V + ((size_t)blockIdx.y * 64 + lrow) * CCH + lu * 16;
    uint32_t smb = smem_u32(&sm[0][0]);
    uint32_t dstA = smb + lrow * AROW + lu * 16;
    uint32_t dstB = smb + A_HALF + lrow * AROW + lu * 16;
    bool doA = (tid < 128);

    // ldmatrix per-lane addresses: tile = (lane>>3): row-half via bit3, k-half via bit4
    uint32_t fRow = (lane & 7) + ((lane >> 3) & 1) * 8;
    uint32_t fColSel = ((lane >> 4) & 1) * 16;
    uint32_t aOffL = (warpM * 16 + fRow) * AROW + fColSel;
    uint32_t bOffL = A_HALF + (warpN * 16 + fRow) * AROW + fColSel;

    auto issue = [&](int chunk, int s) {
        int t = chunk >> 2, kc = chunk & 3;
        if (doA) cpa16(dstA + s * STAGE, Ubase + (size_t)t * UPLANE + kc * 64);
        cpa16(dstB + s * STAGE, Vbase + (size_t)t * VPLANE + kc * 64);
        asm volatile("cp.async.commit_group;" ::: "memory");
    };

    int Y[2][4][4];
    int acc[2][4];
    #pragma unroll
    for (int ni = 0; ni < 2; ni++)
        #pragma unroll
        for (int j = 0; j < 4; j++) {
            acc[ni][j] = 0;
            #pragma unroll
            for (int p = 0; p < 4; p++) Y[ni][j][p] = 0;
        }

    issue(0, 0);
    issue(1, 1);
    int s = 0, s2 = 2;
    #pragma unroll 1
    for (int chunk = 0; chunk < 64; ++chunk) {
        if (chunk < 63) {
            asm volatile("cp.async.wait_group 1;" ::: "memory");
        } else {
            asm volatile("cp.async.wait_group 0;" ::: "memory");
        }
        __syncthreads();
        if (chunk + 2 < 64) issue(chunk + 2, s2);

        uint32_t stageBase = smb + s * STAGE;
        #pragma unroll
        for (int ks = 0; ks < 2; ks++) {
            int ko = ks * 32;
            uint32_t a[4], bm[4];
            ldsm_x4(a,  stageBase + aOffL + ko);
            ldsm_x4(bm, stageBase + bOffL + ko);
            uint32_t b0[2] = { bm[0], bm[2] };
            uint32_t b1[2] = { bm[1], bm[3] };
            mma_s8(acc[0], a, b0);
            mma_s8(acc[1], a, b1);
        }

        if ((chunk & 3) == 3) {
            int t = chunk >> 2;
            int tr = t >> 2, tc = t & 3;
            int cr0 = (tr <= 2) ? 1 : 0;
            int cr1 = (tr == 0) ? 0 : ((tr == 1) ? 1 : -1);
            int cc0 = (tc <= 2) ? 1 : 0;
            int cc1 = (tc == 0) ? 0 : ((tc == 1) ? 1 : -1);
            #pragma unroll
            for (int ni = 0; ni < 2; ni++)
                #pragma unroll
                for (int j = 0; j < 4; j++) {
                    int v = acc[ni][j];
                    Y[ni][j][0] += cr0 * cc0 * v;
                    Y[ni][j][1] += cr0 * cc1 * v;
                    Y[ni][j][2] += cr1 * cc0 * v;
                    Y[ni][j][3] += cr1 * cc1 * v;
                    acc[ni][j] = 0;
                }
        }
        s = (s == 2) ? 0 : s + 1;
        s2 = (s2 == 2) ? 0 : s2 + 1;
    }

    // epilogue: each Mhat element -> 2x2 output pixels, col-major [c][m]
    #pragma unroll
    for (int j = 0; j < 4; j++) {
        int mp = blockIdx.x * 32 + warpM * 16 + g + 8 * (j >> 1);  // wino row
        int n = mp / NT2;
        int rt = mp - n * NT2;
        int ty = rt / 14, tx = rt - ty * 14;
        int hwbase = (2 * ty) * HH28 + 2 * tx;
        int mbase = n * HWSZ + hwbase;
        #pragma unroll
        for (int ni = 0; ni < 2; ni++) {
            int c = blockIdx.y * 64 + warpN * 16 + ni * 8 + 2 * tg + (j & 1);
            size_t obase = (size_t)c * NHW + mbase;
            size_t rbase = ((size_t)n * CCH + c) * HWSZ + hwbase;
            #pragma unroll
            for (int p = 0; p < 4; p++) {
                size_t off = (p >> 1) * HH28 + (p & 1);
                int val = Y[ni][j][p] >> 2;   // exact /4
                if (RESID) {
                    reinterpret_cast<float*>(outp)[obase + off] = (float)val + xres[rbase + off];
                } else {
                    reinterpret_cast<short*>(outp)[obase + off] = (short)val;
                }
            }
        }
    }
}

// -------- stats partials (float, vectorized float4): grid (256, NSLICE)
__global__ void stats_part_f4(const float* __restrict__ ycm,
                              float* __restrict__ ps, float* __restrict__ pq) {
    int c = blockIdx.x, sl = blockIdx.y;
    const float4* p = reinterpret_cast<const float4*>(ycm + (size_t)c * NHW + sl * SLICELEN);
    float s = 0.f, q = 0.f;
    for (int i = threadIdx.x; i < SLICELEN / 4; i += 256) {
        float4 v = p[i];
        s += v.x + v.y + v.z + v.w;
        q += v.x * v.x + v.y * v.y + v.z * v.z + v.w * v.w;
    }
    __shared__ float rs[256], rq[256];
    rs[threadIdx.x] = s; rq[threadIdx.x] = q;
    __syncthreads();
    for (int o = 128; o > 0; o >>= 1) {
        if (threadIdx.x < o) { rs[threadIdx.x] += rs[threadIdx.x + o]; rq[threadIdx.x] += rq[threadIdx.x + o]; }
        __syncthreads();
    }
    if (threadIdx.x == 0) { ps[c * NSLICE + sl] = rs[0]; pq[c * NSLICE + sl] = rq[0]; }
}

// -------- stats partials (short, vectorized short4): grid (256, NSLICE)
__global__ void stats_part_s4(const short* __restrict__ ycm,
                              float* __restrict__ ps, float* __restrict__ pq) {
    int c = blockIdx.x, sl = blockIdx.y;
    const short4* p = reinterpret_cast<const short4*>(ycm + (size_t)c * NHW + sl * SLICELEN);
    float s = 0.f, q = 0.f;
    for (int i = threadIdx.x; i < SLICELEN / 4; i += 256) {
        short4 v = p[i];
        float a = (float)v.x, b = (float)v.y, cc = (float)v.z, d = (float)v.w;
        s += a + b + cc + d;
        q += a * a + b * b + cc * cc + d * d;
    }
    __shared__ float rs[256], rq[256];
    rs[threadIdx.x] = s; rq[threadIdx.x] = q;
    __syncthreads();
    for (int o = 128; o > 0; o >>= 1) {
        if (threadIdx.x < o) { rs[threadIdx.x] += rs[threadIdx.x + o]; rq[threadIdx.x] += rq[threadIdx.x + o]; }
        __syncthreads();
    }
    if (threadIdx.x == 0) { ps[c * NSLICE + sl] = rs[0]; pq[c * NSLICE + sl] = rq[0]; }
}

// -------- stats finalize: 1 block, 256 threads (one channel each)
__global__ void stats_fin(const float* __restrict__ ps, const float* __restrict__ pq,
                          const float* __restrict__ gamma, const float* __restrict__ beta,
                          float* __restrict__ scl, float* __restrict__ bia) {
    int c = threadIdx.x;
    float s = 0.f, q = 0.f;
    #pragma unroll
    for (int j = 0; j < NSLICE; j++) { s += ps[c * NSLICE + j]; q += pq[c * NSLICE + j]; }
    float mean = s / (float)NHW;
    float var  = q / (float)NHW - mean * mean;
    float inv  = rsqrtf(var + 1e-5f);
    float sc   = gamma[c] * inv;
    scl[c] = sc;
    bia[c] = beta[c] - mean * sc;
}

// -------- binarize BN1 output: [c][m] int16 -> [m][c] int8 +-1
__global__ void binarize_kernel(const short* __restrict__ ycm,
                                const float* __restrict__ scl, const float* __restrict__ bia,
                                char* __restrict__ xb2) {
    __shared__ short t[32][33];
    __shared__ float sc[32], bi[32];
    int tx = threadIdx.x, ty = threadIdx.y;
    int c0 = blockIdx.y * 32, m0 = blockIdx.x * 32;
    if (ty == 0) { sc[tx] = scl[c0 + tx]; bi[tx] = bia[c0 + tx]; }
    #pragma unroll
    for (int j = 0; j < 4; j++) {
        int c = c0 + ty + j * 8;
        t[ty + j * 8][tx] = ycm[(size_t)c * NHW + m0 + tx];
    }
    __syncthreads();
    #pragma unroll
    for (int j = 0; j < 4; j++) {
        int m = m0 + ty + j * 8;
        float v = (float)t[tx][ty + j * 8] * sc[tx] + bi[tx];
        xb2[(size_t)m * CCH + c0 + tx] = (v >= 0.f) ? 1 : -1;
    }
}

// -------- final: BN2 + hardtanh + NCHW, float4 vectorized
// grid (NHW/4/256, 256): y = channel, x covers NHW/4 vec elements
__global__ void final_kernel(const float* __restrict__ y2,
                             const float* __restrict__ scl, const float* __restrict__ bia,
                             float* __restrict__ out) {
    int c = blockIdx.y;
    int m4 = blockIdx.x * 256 + threadIdx.x;      // vec index, 0..12543
    float sc = scl[c], bi = bia[c];
    int n = m4 / (HWSZ / 4);
    int hw = (m4 - n * (HWSZ / 4)) * 4;
    float4 v = *reinterpret_cast<const float4*>(y2 + (size_t)c * NHW + m4 * 4);
    v.x = fminf(fmaxf(v.x * sc + bi, -1.f), 1.f);
    v.y = fminf(fmaxf(v.y * sc + bi, -1.f), 1.f);
    v.z = fminf(fmaxf(v.z * sc + bi, -1.f), 1.f);
    v.w = fminf(fmaxf(v.w * sc + bi, -1.f), 1.f);
    *reinterpret_cast<float4*>(out + ((size_t)n * CCH + c) * HWSZ + hw) = v;
}

// ---------------------------------------------------------------- launcher
extern "C" void kernel_launch(void* const* d_in, const int* in_sizes, int n_in,
                              void* d_out, int out_size) {
    const float* x   = (const float*)d_in[0];
    const float* w1  = (const float*)d_in[1];
    const float* w2  = (const float*)d_in[2];
    const float* ga1 = (const float*)d_in[3];
    const float* be1 = (const float*)d_in[4];
    const float* ga2 = (const float*)d_in[5];
    const float* be2 = (const float*)d_in[6];
    float* out = (float*)d_out;

    char *xb1, *xb2, *U, *V1, *V2;
    float *y2, *ps, *pq, *s1, *bi1, *s2, *bi2;
    short* y1;
    cudaGetSymbolAddress((void**)&xb1, g_xb1);
    cudaGetSymbolAddress((void**)&xb2, g_xb2);
    cudaGetSymbolAddress((void**)&U,   g_U);
    cudaGetSymbolAddress((void**)&V1,  g_V1);
    cudaGetSymbolAddress((void**)&V2,  g_V2);
    cudaGetSymbolAddress((void**)&y1,  g_y1);
    cudaGetSymbolAddress((void**)&y2,  g_y2);
    cudaGetSymbolAddress((void**)&ps,  g_ps);
    cudaGetSymbolAddress((void**)&pq,  g_pq);
    cudaGetSymbolAddress((void**)&s1,  g_s1);
    cudaGetSymbolAddress((void**)&bi1, g_bi1);
    cudaGetSymbolAddress((void**)&s2,  g_s2);
    cudaGetSymbolAddress((void**)&bi2, g_bi2);

    prep_x_kernel<<<dim3(25, 8, 64), dim3(32, 8)>>>(x, xb1);
    wino_v_kernel<<<256, 256>>>(w1, V1);
    wino_v_kernel<<<256, 256>>>(w2, V2);

    wino_u_kernel<<<MWIN * 64 / 256, 256>>>(xb1, U);
    wino_gemm<false><<<dim3(392, 4), 256>>>(U, V1, nullptr, (void*)y1);
    stats_part_s4<<<dim3(256, NSLICE), 256>>>(y1, ps, pq);
    stats_fin<<<1, 256>>>(ps, pq, ga1, be1, s1, bi1);
    binarize_kernel<<<dim3(1568, 8), dim3(32, 8)>>>(y1, s1, bi1, xb2);

    wino_u_kernel<<<MWIN * 64 / 256, 256>>>(xb2, U);
    wino_gemm<true><<<dim3(392, 4), 256>>>(U, V2, x, (void*)y2);
    stats_part_f4<<<dim3(256, NSLICE), 256>>>(y2, ps, pq);
    stats_fin<<<1, 256>>>(ps, pq, ga2, be2, s2, bi2);
    final_kernel<<<dim3(NHW / 4 / 256, 256), 256>>>(y2, s2, bi2, out);
}

// round 17
// speedup vs baseline: 1.8360x; 1.0056x over previous
#include <cuda_runtime.h>
#include <cstdint>

#define NIMG 64
#define CCH  256
#define HH28 28
#define HWSZ 784
#define NHW  50176
#define NT2  196          // winograd tiles per image (14x14)
#define MWIN 12544        // 64*196 tile-rows
#define UPLANE (MWIN * CCH)   // bytes per U[t] plane (int8)
#define VPLANE (CCH * CCH)
#define NSLICE 8
#define SLICELEN (NHW / NSLICE)

// wino gemm smem: 3 stages, each A(32 x 80B) + B(64 x 80B)
#define AROW 80
#define A_HALF (32 * AROW)
#define B_HALF (64 * AROW)
#define STAGE (A_HALF + B_HALF)

// ---------------------------------------------------------------- helpers
__device__ __forceinline__ uint32_t smem_u32(const void* p) {
    uint32_t a;
    asm("{ .reg .u64 t; cvta.to.shared.u64 t, %1; cvt.u32.u64 %0, t; }" : "=r"(a) : "l"(p));
    return a;
}
__device__ __forceinline__ void cpa16(uint32_t dst, const void* src) {
    asm volatile("cp.async.cg.shared.global [%0], [%1], 16;"
                 :: "r"(dst), "l"(src) : "memory");
}
__device__ __forceinline__ void mma_s8(int* d, const uint32_t* a, const uint32_t* b) {
    asm volatile(
        "mma.sync.aligned.m16n8k32.row.col.s32.s8.s8.s32 "
        "{%0,%1,%2,%3}, {%4,%5,%6,%7}, {%8,%9}, {%0,%1,%2,%3};"
        : "+r"(d[0]), "+r"(d[1]), "+r"(d[2]), "+r"(d[3])
        : "r"(a[0]), "r"(a[1]), "r"(a[2]), "r"(a[3]), "r"(b[0]), "r"(b[1]));
}
__device__ __forceinline__ void ldsm_x4(uint32_t* r, uint32_t addr) {
    asm volatile("ldmatrix.sync.aligned.m8n8.x4.shared.b16 {%0,%1,%2,%3}, [%4];"
                 : "=r"(r[0]), "=r"(r[1]), "=r"(r[2]), "=r"(r[3]) : "r"(addr));
}

// ---------------------------------------------------------------- scratch
__device__ __align__(256) char  g_xb1[(size_t)NHW * CCH];   // binarized x, NHWC int8
__device__ __align__(256) char  g_xb2[(size_t)NHW * CCH];   // binarized BN1 out, NHWC int8
__device__ __align__(256) char  g_U[(size_t)16 * UPLANE];   // winograd input transform
__device__ __align__(256) char  g_V1[16 * VPLANE];          // winograd weight transform
__device__ __align__(256) char  g_V2[16 * VPLANE];
__device__ short g_y1[(size_t)CCH * NHW];                   // conv1 out, col-major
__device__ float g_y2[(size_t)CCH * NHW];                   // conv2+resid, col-major
__device__ float g_ps[CCH * NSLICE], g_pq[CCH * NSLICE];    // stats partials
__device__ float g_s1[CCH], g_bi1[CCH], g_s2[CCH], g_bi2[CCH];

// -------- K1: binarize x -> NHWC int8 (transpose NCHW -> NHWC)
__global__ void prep_x_kernel(const float* __restrict__ x,
                              char* __restrict__ xb1) {
    __shared__ float t[32][33];
    int tx = threadIdx.x, ty = threadIdx.y;
    int n  = blockIdx.z;
    int c0 = blockIdx.y * 32;
    int p0 = blockIdx.x * 32;
    #pragma unroll
    for (int j = 0; j < 4; j++) {
        int c = c0 + ty + j * 8;
        int p = p0 + tx;
        float v = 0.f;
        if (p < HWSZ) v = x[((size_t)n * CCH + c) * HWSZ + p];
        t[ty + j * 8][tx] = v;
    }
    __syncthreads();
    #pragma unroll
    for (int j = 0; j < 4; j++) {
        int p = p0 + ty + j * 8;
        if (p < HWSZ) {
            float v = t[tx][ty + j * 8];
            xb1[((size_t)(n * HWSZ + p)) * CCH + c0 + tx] = (v >= 0.f) ? 1 : -1;
        }
    }
}

// -------- wino V: w (OIHW f32) -> V[t][cout*256+cin] int8, V = (2G) sign(w) (2G)^T
__global__ void wino_v_kernel(const float* __restrict__ w, char* __restrict__ V) {
    int idx = blockIdx.x * 256 + threadIdx.x;   // cout*256 + cin
    const float* p = w + (size_t)idx * 9;
    int b[3][3];
    #pragma unroll
    for (int i = 0; i < 3; i++)
        #pragma unroll
        for (int j = 0; j < 3; j++)
            b[i][j] = (p[i * 3 + j] >= 0.f) ? 1 : -1;
    int g[4][3];
    #pragma unroll
    for (int j = 0; j < 3; j++) {
        g[0][j] = 2 * b[0][j];
        g[1][j] = b[0][j] + b[1][j] + b[2][j];
        g[2][j] = b[0][j] - b[1][j] + b[2][j];
        g[3][j] = 2 * b[2][j];
    }
    #pragma unroll
    for (int i = 0; i < 4; i++) {
        int v0 = 2 * g[i][0];
        int v1 = g[i][0] + g[i][1] + g[i][2];
        int v2 = g[i][0] - g[i][1] + g[i][2];
        int v3 = 2 * g[i][2];
        V[(size_t)(i * 4 + 0) * VPLANE + idx] = (char)v0;
        V[(size_t)(i * 4 + 1) * VPLANE + idx] = (char)v1;
        V[(size_t)(i * 4 + 2) * VPLANE + idx] = (char)v2;
        V[(size_t)(i * 4 + 3) * VPLANE + idx] = (char)v3;
    }
}

// -------- wino U: xb NHWC int8 -> U[t][tile*256+c] int8  (B^T d B, |U|<=4)
__global__ void wino_u_kernel(const char* __restrict__ xb, char* __restrict__ U) {
    int item = blockIdx.x * 256 + threadIdx.x;   // tile*64 + cgroup
    int tile = item >> 6;
    int cg = item & 63;                          // 4 channels per thread
    int n = tile / NT2;
    int rt = tile - n * NT2;
    int ty = rt / 14, tx = rt - ty * 14;
    int h0 = 2 * ty - 1, w0 = 2 * tx - 1;
    const char* base = xb + ((size_t)n * HWSZ) * CCH + cg * 4;

    uint32_t d[4][4];
    #pragma unroll
    for (int i = 0; i < 4; i++) {
        int h = h0 + i;
        #pragma unroll
        for (int j = 0; j < 4; j++) {
            int w = w0 + j;
            d[i][j] = (((unsigned)h < 28u) & ((unsigned)w < 28u))
                ? *reinterpret_cast<const uint32_t*>(base + (size_t)(h * HH28 + w) * CCH)
                : 0u;
        }
    }
    uint32_t r[4][4];
    #pragma unroll
    for (int j = 0; j < 4; j++) {
        r[0][j] = __vsub4(d[0][j], d[2][j]);
        r[1][j] = __vadd4(d[1][j], d[2][j]);
        r[2][j] = __vsub4(d[2][j], d[1][j]);
        r[3][j] = __vsub4(d[1][j], d[3][j]);
    }
    #pragma unroll
    for (int i = 0; i < 4; i++) {
        uint32_t u0 = __vsub4(r[i][0], r[i][2]);
        uint32_t u1 = __vadd4(r[i][1], r[i][2]);
        uint32_t u2 = __vsub4(r[i][2], r[i][1]);
        uint32_t u3 = __vsub4(r[i][1], r[i][3]);
        size_t off = (size_t)tile * CCH + cg * 4;
        *reinterpret_cast<uint32_t*>(U + (size_t)(i * 4 + 0) * UPLANE + off) = u0;
        *reinterpret_cast<uint32_t*>(U + (size_t)(i * 4 + 1) * UPLANE + off) = u1;
        *reinterpret_cast<uint32_t*>(U + (size_t)(i * 4 + 2) * UPLANE + off) = u2;
        *reinterpret_cast<uint32_t*>(U + (size_t)(i * 4 + 3) * UPLANE + off) = u3;
    }
}

// -------- wino GEMM: for t in 0..15: Mhat = U[t]*V[t]^T, fold into Y, write col-major
// grid (392, 4): M-tile 32, N-tile 64; warps 2x4, warp tile 16x16
// 3-stage cp.async ring, ldmatrix fragment loads, occupancy 4
template <bool RESID>
__global__ void __launch_bounds__(256, 4)
wino_gemm(const char* __restrict__ U,
          const char* __restrict__ V,
          const float* __restrict__ xres,
          void* __restrict__ outp) {
    __shared__ __align__(16) char sm[3][STAGE];

    int tid = threadIdx.x, wid = tid >> 5, lane = tid & 31;
    int g = lane >> 2, tg = lane & 3;
    int warpM = wid & 1, warpN = wid >> 1;    // 2 x 4 warps, warp tile 16x16

    int lrow = tid >> 2, lu = tid & 3;
    const char* Ubase = U + ((size_t)blockIdx.x * 32 + lrow) * CCH + lu * 16;   // valid for tid<128
    const char* Vbase = V + ((size_t)blockIdx.y * 64 + lrow) * CCH + lu * 16;
    uint32_t smb = smem_u32(&sm[0][0]);
    uint32_t dstA = smb + lrow * AROW + lu * 16;
    uint32_t dstB = smb + A_HALF + lrow * AROW + lu * 16;
    bool doA = (tid < 128);

    // ldmatrix per-lane addresses: tile = (lane>>3): row-half via bit3, k-half via bit4
    uint32_t fRow = (lane & 7) + ((lane >> 3) & 1) * 8;
    uint32_t fColSel = ((lane >> 4) & 1) * 16;
    uint32_t aOffL = (warpM * 16 + fRow) * AROW + fColSel;
    uint32_t bOffL = A_HALF + (warpN * 16 + fRow) * AROW + fColSel;

    auto issue = [&](int chunk, int s) {
        int t = chunk >> 2, kc = chunk & 3;
        if (doA) cpa16(dstA + s * STAGE, Ubase + (size_t)t * UPLANE + kc * 64);
        cpa16(dstB + s * STAGE, Vbase + (size_t)t * VPLANE + kc * 64);
        asm volatile("cp.async.commit_group;" ::: "memory");
    };

    int Y[2][4][4];
    int acc[2][4];
    #pragma unroll
    for (int ni = 0; ni < 2; ni++)
        #pragma unroll
        for (int j = 0; j < 4; j++) {
            acc[ni][j] = 0;
            #pragma unroll
            for (int p = 0; p < 4; p++) Y[ni][j][p] = 0;
        }

    issue(0, 0);
    issue(1, 1);
    int s = 0, s2 = 2;
    #pragma unroll 1
    for (int chunk = 0; chunk < 64; ++chunk) {
        if (chunk < 63) {
            asm volatile("cp.async.wait_group 1;" ::: "memory");
        } else {
            asm volatile("cp.async.wait_group 0;" ::: "memory");
        }
        __syncthreads();
        if (chunk + 2 < 64) issue(chunk + 2, s2);

        uint32_t stageBase = smb + s * STAGE;
        #pragma unroll
        for (int ks = 0; ks < 2; ks++) {
            int ko = ks * 32;
            uint32_t a[4], bm[4];
            ldsm_x4(a,  stageBase + aOffL + ko);
            ldsm_x4(bm, stageBase + bOffL + ko);
            uint32_t b0[2] = { bm[0], bm[2] };
            uint32_t b1[2] = { bm[1], bm[3] };
            mma_s8(acc[0], a, b0);
            mma_s8(acc[1], a, b1);
        }

        if ((chunk & 3) == 3) {
            int t = chunk >> 2;
            int tr = t >> 2, tc = t & 3;
            int cr0 = (tr <= 2) ? 1 : 0;
            int cr1 = (tr == 0) ? 0 : ((tr == 1) ? 1 : -1);
            int cc0 = (tc <= 2) ? 1 : 0;
            int cc1 = (tc == 0) ? 0 : ((tc == 1) ? 1 : -1);
            #pragma unroll
            for (int ni = 0; ni < 2; ni++)
                #pragma unroll
                for (int j = 0; j < 4; j++) {
                    int v = acc[ni][j];
                    Y[ni][j][0] += cr0 * cc0 * v;
                    Y[ni][j][1] += cr0 * cc1 * v;
                    Y[ni][j][2] += cr1 * cc0 * v;
                    Y[ni][j][3] += cr1 * cc1 * v;
                    acc[ni][j] = 0;
                }
        }
        s = (s == 2) ? 0 : s + 1;
        s2 = (s2 == 2) ? 0 : s2 + 1;
    }

    // epilogue: each Mhat element -> 2x2 output pixels, col-major [c][m]
    #pragma unroll
    for (int j = 0; j < 4; j++) {
        int mp = blockIdx.x * 32 + warpM * 16 + g + 8 * (j >> 1);  // wino row
        int n = mp / NT2;
        int rt = mp - n * NT2;
        int ty = rt / 14, tx = rt - ty * 14;
        int hwbase = (2 * ty) * HH28 + 2 * tx;
        int mbase = n * HWSZ + hwbase;
        #pragma unroll
        for (int ni = 0; ni < 2; ni++) {
            int c = blockIdx.y * 64 + warpN * 16 + ni * 8 + 2 * tg + (j & 1);
            size_t obase = (size_t)c * NHW + mbase;
            size_t rbase = ((size_t)n * CCH + c) * HWSZ + hwbase;
            #pragma unroll
            for (int p = 0; p < 4; p++) {
                size_t off = (p >> 1) * HH28 + (p & 1);
                int val = Y[ni][j][p] >> 2;   // exact /4
                if (RESID) {
                    reinterpret_cast<float*>(outp)[obase + off] = (float)val + xres[rbase + off];
                } else {
                    reinterpret_cast<short*>(outp)[obase + off] = (short)val;
                }
            }
        }
    }
}

// -------- stats partials (float, vectorized float4): grid (256, NSLICE)
__global__ void stats_part_f4(const float* __restrict__ ycm,
                              float* __restrict__ ps, float* __restrict__ pq) {
    int c = blockIdx.x, sl = blockIdx.y;
    const float4* p = reinterpret_cast<const float4*>(ycm + (size_t)c * NHW + sl * SLICELEN);
    float s = 0.f, q = 0.f;
    for (int i = threadIdx.x; i < SLICELEN / 4; i += 256) {
        float4 v = p[i];
        s += v.x + v.y + v.z + v.w;
        q += v.x * v.x + v.y * v.y + v.z * v.z + v.w * v.w;
    }
    __shared__ float rs[256], rq[256];
    rs[threadIdx.x] = s; rq[threadIdx.x] = q;
    __syncthreads();
    for (int o = 128; o > 0; o >>= 1) {
        if (threadIdx.x < o) { rs[threadIdx.x] += rs[threadIdx.x + o]; rq[threadIdx.x] += rq[threadIdx.x + o]; }
        __syncthreads();
    }
    if (threadIdx.x == 0) { ps[c * NSLICE + sl] = rs[0]; pq[c * NSLICE + sl] = rq[0]; }
}

// -------- stats partials (short, vectorized short4): grid (256, NSLICE)
__global__ void stats_part_s4(const short* __restrict__ ycm,
                              float* __restrict__ ps, float* __restrict__ pq) {
    int c = blockIdx.x, sl = blockIdx.y;
    const short4* p = reinterpret_cast<const short4*>(ycm + (size_t)c * NHW + sl * SLICELEN);
    float s = 0.f, q = 0.f;
    for (int i = threadIdx.x; i < SLICELEN / 4; i += 256) {
        short4 v = p[i];
        float a = (float)v.x, b = (float)v.y, cc = (float)v.z, d = (float)v.w;
        s += a + b + cc + d;
        q += a * a + b * b + cc * cc + d * d;
    }
    __shared__ float rs[256], rq[256];
    rs[threadIdx.x] = s; rq[threadIdx.x] = q;
    __syncthreads();
    for (int o = 128; o > 0; o >>= 1) {
        if (threadIdx.x < o) { rs[threadIdx.x] += rs[threadIdx.x + o]; rq[threadIdx.x] += rq[threadIdx.x + o]; }
        __syncthreads();
    }
    if (threadIdx.x == 0) { ps[c * NSLICE + sl] = rs[0]; pq[c * NSLICE + sl] = rq[0]; }
}

// -------- stats finalize: 1 block, 256 threads (one channel each)
__global__ void stats_fin(const float* __restrict__ ps, const float* __restrict__ pq,
                          const float* __restrict__ gamma, const float* __restrict__ beta,
                          float* __restrict__ scl, float* __restrict__ bia) {
    int c = threadIdx.x;
    float s = 0.f, q = 0.f;
    #pragma unroll
    for (int j = 0; j < NSLICE; j++) { s += ps[c * NSLICE + j]; q += pq[c * NSLICE + j]; }
    float mean = s / (float)NHW;
    float var  = q / (float)NHW - mean * mean;
    float inv  = rsqrtf(var + 1e-5f);
    float sc   = gamma[c] * inv;
    scl[c] = sc;
    bia[c] = beta[c] - mean * sc;
}

// -------- binarize BN1 output: [c][m] int16 -> [m][c] int8 +-1
__global__ void binarize_kernel(const short* __restrict__ ycm,
                                const float* __restrict__ scl, const float* __restrict__ bia,
                                char* __restrict__ xb2) {
    __shared__ short t[32][33];
    __shared__ float sc[32], bi[32];
    int tx = threadIdx.x, ty = threadIdx.y;
    int c0 = blockIdx.y * 32, m0 = blockIdx.x * 32;
    if (ty == 0) { sc[tx] = scl[c0 + tx]; bi[tx] = bia[c0 + tx]; }
    #pragma unroll
    for (int j = 0; j < 4; j++) {
        int c = c0 + ty + j * 8;
        t[ty + j * 8][tx] = ycm[(size_t)c * NHW + m0 + tx];
    }
    __syncthreads();
    #pragma unroll
    for (int j = 0; j < 4; j++) {
        int m = m0 + ty + j * 8;
        float v = (float)t[tx][ty + j * 8] * sc[tx] + bi[tx];
        xb2[(size_t)m * CCH + c0 + tx] = (v >= 0.f) ? 1 : -1;
    }
}

// -------- final: BN2 + hardtanh + NCHW, float4 vectorized
// grid (NHW/4/256, 256): y = channel, x covers NHW/4 vec elements
__global__ void final_kernel(const float* __restrict__ y2,
                             const float* __restrict__ scl, const float* __restrict__ bia,
                             float* __restrict__ out) {
    int c = blockIdx.y;
    int m4 = blockIdx.x * 256 + threadIdx.x;      // vec index, 0..12543
    float sc = scl[c], bi = bia[c];
    int n = m4 / (HWSZ / 4);
    int hw = (m4 - n * (HWSZ / 4)) * 4;
    float4 v = *reinterpret_cast<const float4*>(y2 + (size_t)c * NHW + m4 * 4);
    v.x = fminf(fmaxf(v.x * sc + bi, -1.f), 1.f);
    v.y = fminf(fmaxf(v.y * sc + bi, -1.f), 1.f);
    v.z = fminf(fmaxf(v.z * sc + bi, -1.f), 1.f);
    v.w = fminf(fmaxf(v.w * sc + bi, -1.f), 1.f);
    *reinterpret_cast<float4*>(out + ((size_t)n * CCH + c) * HWSZ + hw) = v;
}

// ---------------------------------------------------------------- launcher
extern "C" void kernel_launch(void* const* d_in, const int* in_sizes, int n_in,
                              void* d_out, int out_size) {
    const float* x   = (const float*)d_in[0];
    const float* w1  = (const float*)d_in[1];
    const float* w2  = (const float*)d_in[2];
    const float* ga1 = (const float*)d_in[3];
    const float* be1 = (const float*)d_in[4];
    const float* ga2 = (const float*)d_in[5];
    const float* be2 = (const float*)d_in[6];
    float* out = (float*)d_out;

    char *xb1, *xb2, *U, *V1, *V2;
    float *y2, *ps, *pq, *s1, *bi1, *s2, *bi2;
    short* y1;
    cudaGetSymbolAddress((void**)&xb1, g_xb1);
    cudaGetSymbolAddress((void**)&xb2, g_xb2);
    cudaGetSymbolAddress((void**)&U,   g_U);
    cudaGetSymbolAddress((void**)&V1,  g_V1);
    cudaGetSymbolAddress((void**)&V2,  g_V2);
    cudaGetSymbolAddress((void**)&y1,  g_y1);
    cudaGetSymbolAddress((void**)&y2,  g_y2);
    cudaGetSymbolAddress((void**)&ps,  g_ps);
    cudaGetSymbolAddress((void**)&pq,  g_pq);
    cudaGetSymbolAddress((void**)&s1,  g_s1);
    cudaGetSymbolAddress((void**)&bi1, g_bi1);
    cudaGetSymbolAddress((void**)&s2,  g_s2);
    cudaGetSymbolAddress((void**)&bi2, g_bi2);

    prep_x_kernel<<<dim3(25, 8, 64), dim3(32, 8)>>>(x, xb1);
    wino_v_kernel<<<256, 256>>>(w1, V1);
    wino_v_kernel<<<256, 256>>>(w2, V2);

    wino_u_kernel<<<MWIN * 64 / 256, 256>>>(xb1, U);
    wino_gemm<false><<<dim3(392, 4), 256>>>(U, V1, nullptr, (void*)y1);
    stats_part_s4<<<dim3(256, NSLICE), 256>>>(y1, ps, pq);
    stats_fin<<<1, 256>>>(ps, pq, ga1, be1, s1, bi1);
    binarize_kernel<<<dim3(1568, 8), dim3(32, 8)>>>(y1, s1, bi1, xb2);

    wino_u_kernel<<<MWIN * 64 / 256, 256>>>(xb2, U);
    wino_gemm<true><<<dim3(392, 4), 256>>>(U, V2, x, (void*)y2);
    stats_part_f4<<<dim3(256, NSLICE), 256>>>(y2, ps, pq);
    stats_fin<<<1, 256>>>(ps, pq, ga2, be2, s2, bi2);
    final_kernel<<<dim3(NHW / 4 / 256, 256), 256>>>(y2, s2, bi2, out);
}